// round 1
// baseline (speedup 1.0000x reference)
#include <cuda_runtime.h>
#include <math.h>

#define BATCH   2
#define C_DIM   256
#define N_TOK   4096
#define HEADS   4
#define HD      64
#define GROUPS  8
#define GSZ     (C_DIM / GROUPS)           // 32 channels per group
#define GCNT    (GSZ * N_TOK)              // 131072 elements per (b,g)

// -------- scratch (static __device__ — no allocations allowed) --------
__device__ float g_stats[BATCH * GROUPS * 2];            // mean, rstd
__device__ float g_q[BATCH * HEADS * N_TOK * HD];
__device__ float g_k[BATCH * HEADS * N_TOK * HD];
__device__ float g_v[BATCH * HEADS * N_TOK * HD];
__device__ float g_o[BATCH * HEADS * N_TOK * HD];

__device__ __forceinline__ float fast_exp2(float x) {
    float r;
    asm("ex2.approx.ftz.f32 %0, %1;" : "=f"(r) : "f"(x));
    return r;
}

// ==================== 1) GroupNorm statistics ====================
// One block per (b, g). The (b,g) slab is a contiguous 131072-float region.
__global__ __launch_bounds__(512) void gn_stats_kernel(const float* __restrict__ x) {
    int bg = blockIdx.x;
    const float4* p = (const float4*)(x + (size_t)bg * GCNT);
    const int n4 = GCNT / 4;
    float s = 0.f, ss = 0.f;
    for (int i = threadIdx.x; i < n4; i += 512) {
        float4 v = p[i];
        s  += v.x + v.y + v.z + v.w;
        ss += v.x * v.x + v.y * v.y + v.z * v.z + v.w * v.w;
    }
    __shared__ float sh1[512], sh2[512];
    int tid = threadIdx.x;
    sh1[tid] = s; sh2[tid] = ss;
    __syncthreads();
    for (int o = 256; o > 0; o >>= 1) {
        if (tid < o) { sh1[tid] += sh1[tid + o]; sh2[tid] += sh2[tid + o]; }
        __syncthreads();
    }
    if (tid == 0) {
        float mean = sh1[0] * (1.f / GCNT);
        float var  = sh2[0] * (1.f / GCNT) - mean * mean;
        g_stats[bg * 2]     = mean;
        g_stats[bg * 2 + 1] = rsqrtf(var + 1e-5f);
    }
}

// ==================== 2) QKV GEMM fused with GN apply ====================
// out[b,o,n] = sum_c w_qkv[o,c] * gn(x[b,c,n]) + b_qkv[o]
// Written directly into q/k/v as [b, head, n, d].
// Tile: BM=64 (o), BN=64 (n), BK=32 (c). 256 threads, 4x4 micro-tile.
__global__ __launch_bounds__(256) void qkv_kernel(
    const float* __restrict__ x, const float* __restrict__ gamma,
    const float* __restrict__ beta, const float* __restrict__ w,
    const float* __restrict__ bias)
{
    __shared__ float As[32][68];   // A transposed: As[k][m]
    __shared__ float Bs[32][68];   // Bs[k][n]
    int n0 = blockIdx.x * 64;
    int m0 = blockIdx.y * 64;
    int b  = blockIdx.z;
    int tid = threadIdx.x;
    int tx = tid & 15, ty = tid >> 4;

    const float* xb = x + (size_t)b * C_DIM * N_TOK;
    float acc[4][4] = {};

    for (int k0 = 0; k0 < C_DIM; k0 += 32) {
        // load W tile transposed
        {
            int k = tid & 31, i0 = tid >> 5;
            #pragma unroll
            for (int r = 0; r < 8; r++) {
                int i = i0 + r * 8;
                As[k][i] = w[(m0 + i) * C_DIM + k0 + k];
            }
        }
        // load x tile with GroupNorm applied on the fly
        {
            int nn = tid & 63, kk0 = tid >> 6;
            #pragma unroll
            for (int r = 0; r < 8; r++) {
                int kk = kk0 + r * 4;
                int c  = k0 + kk;
                int sg = (b * GROUPS + (c >> 5)) * 2;
                float mean = g_stats[sg], rstd = g_stats[sg + 1];
                float a  = rstd * gamma[c];
                float bb = beta[c] - mean * a;
                Bs[kk][nn] = xb[(size_t)c * N_TOK + n0 + nn] * a + bb;
            }
        }
        __syncthreads();
        #pragma unroll
        for (int k = 0; k < 32; k++) {
            float av[4], bv[4];
            *(float4*)av = *(const float4*)&As[k][ty * 4];
            *(float4*)bv = *(const float4*)&Bs[k][tx * 4];
            #pragma unroll
            for (int i = 0; i < 4; i++)
                #pragma unroll
                for (int j = 0; j < 4; j++)
                    acc[i][j] += av[i] * bv[j];
        }
        __syncthreads();
    }

    // Epilogue: route to q/k/v in [b, h, n, d] layout. Whole block shares
    // (which, head) since m0 is a multiple of 64.
    int mbase = m0 + ty * 4;
    int which = mbase >> 8;          // 0:q 1:k 2:v
    int mm    = mbase & 255;
    int h     = mm >> 6;
    int d0    = mm & 63;
    float* dst = (which == 0) ? g_q : (which == 1) ? g_k : g_v;
    float bi[4];
    #pragma unroll
    for (int i = 0; i < 4; i++) bi[i] = bias[mbase + i];
    #pragma unroll
    for (int j = 0; j < 4; j++) {
        int n = n0 + tx * 4 + j;
        float4 v = make_float4(acc[0][j] + bi[0], acc[1][j] + bi[1],
                               acc[2][j] + bi[2], acc[3][j] + bi[3]);
        *(float4*)&dst[(((size_t)b * HEADS + h) * N_TOK + n) * HD + d0] = v;
    }
}

// ==================== 3) Flash attention ====================
// 1 thread = 1 query row. 128 rows per block, stream K/V in 64-key tiles.
// exp2-domain online softmax; scale*log2(e) folded into q.
__global__ __launch_bounds__(128, 2) void attn_kernel() {
    __shared__ float Ks[64 * HD];
    __shared__ float Vs[64 * HD];
    int bh  = blockIdx.y;
    int row = blockIdx.x * 128 + threadIdx.x;

    const float QSCALE = 0.125f * 1.4426950408889634f;  // hd^-0.5 * log2(e)
    const float4* qp = (const float4*)(g_q + ((size_t)bh * N_TOK + row) * HD);
    float4 q[16];
    #pragma unroll
    for (int i = 0; i < 16; i++) {
        float4 t = qp[i];
        q[i] = make_float4(t.x * QSCALE, t.y * QSCALE, t.z * QSCALE, t.w * QSCALE);
    }

    float O[64];
    #pragma unroll
    for (int i = 0; i < 64; i++) O[i] = 0.f;
    float m = -1e30f, l = 0.f;

    const float4* kbase = (const float4*)(g_k + (size_t)bh * N_TOK * HD);
    const float4* vbase = (const float4*)(g_v + (size_t)bh * N_TOK * HD);
    float4* kd = (float4*)Ks;
    float4* vd = (float4*)Vs;

    for (int kt = 0; kt < N_TOK / 64; kt++) {
        __syncthreads();
        int base = kt * 64 * (HD / 4);
        #pragma unroll
        for (int p = 0; p < 8; p++) {
            int idx = threadIdx.x + p * 128;
            kd[idx] = kbase[base + idx];
            vd[idx] = vbase[base + idx];
        }
        __syncthreads();

        #pragma unroll
        for (int cc = 0; cc < 4; cc++) {
            float s[16];
            #pragma unroll
            for (int j = 0; j < 16; j++) {
                const float4* kr = (const float4*)(Ks + (cc * 16 + j) * HD);
                float a0 = 0.f, a1 = 0.f;
                #pragma unroll
                for (int d = 0; d < 16; d += 2) {
                    float4 k0 = kr[d], k1 = kr[d + 1];
                    a0 += q[d].x * k0.x + q[d].y * k0.y + q[d].z * k0.z + q[d].w * k0.w;
                    a1 += q[d+1].x * k1.x + q[d+1].y * k1.y + q[d+1].z * k1.z + q[d+1].w * k1.w;
                }
                s[j] = a0 + a1;
            }
            float cmax = s[0];
            #pragma unroll
            for (int j = 1; j < 16; j++) cmax = fmaxf(cmax, s[j]);
            float mn = fmaxf(m, cmax);
            float corr = fast_exp2(m - mn);
            l *= corr;
            #pragma unroll
            for (int d = 0; d < 64; d++) O[d] *= corr;
            #pragma unroll
            for (int j = 0; j < 16; j++) {
                float p = fast_exp2(s[j] - mn);
                l += p;
                const float4* vr = (const float4*)(Vs + (cc * 16 + j) * HD);
                #pragma unroll
                for (int d = 0; d < 16; d++) {
                    float4 vv = vr[d];
                    O[d*4+0] += p * vv.x;
                    O[d*4+1] += p * vv.y;
                    O[d*4+2] += p * vv.z;
                    O[d*4+3] += p * vv.w;
                }
            }
            m = mn;
        }
    }

    float inv = 1.f / l;
    float4* op = (float4*)(g_o + ((size_t)bh * N_TOK + row) * HD);
    #pragma unroll
    for (int i = 0; i < 16; i++)
        op[i] = make_float4(O[i*4] * inv, O[i*4+1] * inv, O[i*4+2] * inv, O[i*4+3] * inv);
}

// ==================== 4) proj GEMM + bias + residual ====================
__global__ __launch_bounds__(256) void proj_kernel(
    const float* __restrict__ x, const float* __restrict__ w,
    const float* __restrict__ bias, float* __restrict__ out)
{
    __shared__ float As[32][68];
    __shared__ float Bs[32][68];
    int n0 = blockIdx.x * 64;
    int m0 = blockIdx.y * 64;
    int b  = blockIdx.z;
    int tid = threadIdx.x;
    int tx = tid & 15, ty = tid >> 4;

    float acc[4][4] = {};
    for (int k0 = 0; k0 < C_DIM; k0 += 32) {
        {
            int k = tid & 31, i0 = tid >> 5;
            #pragma unroll
            for (int r = 0; r < 8; r++) {
                int i = i0 + r * 8;
                As[k][i] = w[(m0 + i) * C_DIM + k0 + k];
            }
        }
        {
            int nn = tid & 63, kk0 = tid >> 6;
            #pragma unroll
            for (int r = 0; r < 8; r++) {
                int kk = kk0 + r * 4;
                int c  = k0 + kk;
                // attention out channel c = h*64 + d, stored [b,h,n,d]
                Bs[kk][nn] = g_o[(((size_t)b * HEADS + (c >> 6)) * N_TOK + n0 + nn) * HD + (c & 63)];
            }
        }
        __syncthreads();
        #pragma unroll
        for (int k = 0; k < 32; k++) {
            float av[4], bv[4];
            *(float4*)av = *(const float4*)&As[k][ty * 4];
            *(float4*)bv = *(const float4*)&Bs[k][tx * 4];
            #pragma unroll
            for (int i = 0; i < 4; i++)
                #pragma unroll
                for (int j = 0; j < 4; j++)
                    acc[i][j] += av[i] * bv[j];
        }
        __syncthreads();
    }

    #pragma unroll
    for (int i = 0; i < 4; i++) {
        int mo = m0 + ty * 4 + i;
        float bi = bias[mo];
        size_t rowbase = (size_t)b * C_DIM * N_TOK + (size_t)mo * N_TOK + n0 + tx * 4;
        float4 res = *(const float4*)&x[rowbase];
        float4 v = make_float4(acc[i][0] + bi + res.x, acc[i][1] + bi + res.y,
                               acc[i][2] + bi + res.z, acc[i][3] + bi + res.w);
        *(float4*)&out[rowbase] = v;
    }
}

// ==================== launch ====================
extern "C" void kernel_launch(void* const* d_in, const int* in_sizes, int n_in,
                              void* d_out, int out_size) {
    const float* x      = (const float*)d_in[0];
    const float* gamma  = (const float*)d_in[1];
    const float* beta   = (const float*)d_in[2];
    const float* w_qkv  = (const float*)d_in[3];
    const float* b_qkv  = (const float*)d_in[4];
    const float* w_proj = (const float*)d_in[5];
    const float* b_proj = (const float*)d_in[6];
    float* out = (float*)d_out;

    gn_stats_kernel<<<BATCH * GROUPS, 512>>>(x);
    qkv_kernel<<<dim3(N_TOK / 64, (3 * C_DIM) / 64, BATCH), 256>>>(x, gamma, beta, w_qkv, b_qkv);
    attn_kernel<<<dim3(N_TOK / 128, BATCH * HEADS), 128>>>();
    proj_kernel<<<dim3(N_TOK / 64, C_DIM / 64, BATCH), 256>>>(x, w_proj, b_proj, out);
}

// round 2
// speedup vs baseline: 5.1559x; 5.1559x over previous
#include <cuda_runtime.h>
#include <math.h>
#include <stdint.h>

#define BATCH   2
#define C_DIM   256
#define N_TOK   4096
#define HEADS   4
#define HD      64
#define GROUPS  8
#define GSZ     (C_DIM / GROUPS)           // 32 channels per group
#define GCNT    (GSZ * N_TOK)              // 131072 elements per (b,g)

// -------- scratch (static __device__ — no allocations allowed) --------
__device__ float g_stats[BATCH * GROUPS * 2];            // mean, rstd
__device__ float g_q[BATCH * HEADS * N_TOK * HD];
__device__ float g_k[BATCH * HEADS * N_TOK * HD];
__device__ float g_v[BATCH * HEADS * N_TOK * HD];
__device__ float g_o[BATCH * HEADS * N_TOK * HD];

__device__ __forceinline__ float fast_exp2(float x) {
    float r;
    asm("ex2.approx.ftz.f32 %0, %1;" : "=f"(r) : "f"(x));
    return r;
}
__device__ __forceinline__ uint32_t to_tf32(float x) {
    uint32_t r;
    asm("cvt.rna.tf32.f32 %0, %1;" : "=r"(r) : "f"(x));
    return r;
}
__device__ __forceinline__ void mma_tf32(float& c0, float& c1, float& c2, float& c3,
                                         uint32_t a0, uint32_t a1, uint32_t a2, uint32_t a3,
                                         uint32_t b0, uint32_t b1) {
    asm volatile(
        "mma.sync.aligned.m16n8k8.row.col.f32.tf32.tf32.f32 "
        "{%0,%1,%2,%3}, {%4,%5,%6,%7}, {%8,%9}, {%0,%1,%2,%3};"
        : "+f"(c0), "+f"(c1), "+f"(c2), "+f"(c3)
        : "r"(a0), "r"(a1), "r"(a2), "r"(a3), "r"(b0), "r"(b1));
}

// ==================== 1) GroupNorm statistics ====================
__global__ __launch_bounds__(512) void gn_stats_kernel(const float* __restrict__ x) {
    int bg = blockIdx.x;
    const float4* p = (const float4*)(x + (size_t)bg * GCNT);
    const int n4 = GCNT / 4;
    float s = 0.f, ss = 0.f;
    for (int i = threadIdx.x; i < n4; i += 512) {
        float4 v = p[i];
        s  += v.x + v.y + v.z + v.w;
        ss += v.x * v.x + v.y * v.y + v.z * v.z + v.w * v.w;
    }
    __shared__ float sh1[512], sh2[512];
    int tid = threadIdx.x;
    sh1[tid] = s; sh2[tid] = ss;
    __syncthreads();
    for (int o = 256; o > 0; o >>= 1) {
        if (tid < o) { sh1[tid] += sh1[tid + o]; sh2[tid] += sh2[tid + o]; }
        __syncthreads();
    }
    if (tid == 0) {
        float mean = sh1[0] * (1.f / GCNT);
        float var  = sh2[0] * (1.f / GCNT) - mean * mean;
        g_stats[bg * 2]     = mean;
        g_stats[bg * 2 + 1] = rsqrtf(var + 1e-5f);
    }
}

// ==================== 2) QKV GEMM fused with GN apply ====================
// Stores Q/K/V pre-rounded to TF32 so the HMMA truncation is exact.
__global__ __launch_bounds__(256) void qkv_kernel(
    const float* __restrict__ x, const float* __restrict__ gamma,
    const float* __restrict__ beta, const float* __restrict__ w,
    const float* __restrict__ bias)
{
    __shared__ float As[32][68];
    __shared__ float Bs[32][68];
    int n0 = blockIdx.x * 64;
    int m0 = blockIdx.y * 64;
    int b  = blockIdx.z;
    int tid = threadIdx.x;
    int tx = tid & 15, ty = tid >> 4;

    const float* xb = x + (size_t)b * C_DIM * N_TOK;
    float acc[4][4] = {};

    for (int k0 = 0; k0 < C_DIM; k0 += 32) {
        {
            int k = tid & 31, i0 = tid >> 5;
            #pragma unroll
            for (int r = 0; r < 8; r++) {
                int i = i0 + r * 8;
                As[k][i] = w[(m0 + i) * C_DIM + k0 + k];
            }
        }
        {
            int nn = tid & 63, kk0 = tid >> 6;
            #pragma unroll
            for (int r = 0; r < 8; r++) {
                int kk = kk0 + r * 4;
                int c  = k0 + kk;
                int sg = (b * GROUPS + (c >> 5)) * 2;
                float mean = g_stats[sg], rstd = g_stats[sg + 1];
                float a  = rstd * gamma[c];
                float bb = beta[c] - mean * a;
                Bs[kk][nn] = xb[(size_t)c * N_TOK + n0 + nn] * a + bb;
            }
        }
        __syncthreads();
        #pragma unroll
        for (int k = 0; k < 32; k++) {
            float av[4], bv[4];
            *(float4*)av = *(const float4*)&As[k][ty * 4];
            *(float4*)bv = *(const float4*)&Bs[k][tx * 4];
            #pragma unroll
            for (int i = 0; i < 4; i++)
                #pragma unroll
                for (int j = 0; j < 4; j++)
                    acc[i][j] += av[i] * bv[j];
        }
        __syncthreads();
    }

    int mbase = m0 + ty * 4;
    int which = mbase >> 8;          // 0:q 1:k 2:v
    int mm    = mbase & 255;
    int h     = mm >> 6;
    int d0    = mm & 63;
    float* dst = (which == 0) ? g_q : (which == 1) ? g_k : g_v;
    float bi[4];
    #pragma unroll
    for (int i = 0; i < 4; i++) bi[i] = bias[mbase + i];
    #pragma unroll
    for (int j = 0; j < 4; j++) {
        int n = n0 + tx * 4 + j;
        float4 v = make_float4(
            __uint_as_float(to_tf32(acc[0][j] + bi[0])),
            __uint_as_float(to_tf32(acc[1][j] + bi[1])),
            __uint_as_float(to_tf32(acc[2][j] + bi[2])),
            __uint_as_float(to_tf32(acc[3][j] + bi[3])));
        *(float4*)&dst[(((size_t)b * HEADS + h) * N_TOK + n) * HD + d0] = v;
    }
}

// ==================== 3) Flash attention (TF32 mma.sync) ====================
// 8 warps/block; warp owns a 16x64 Q tile + register O. K/V streamed in
// 64-key smem tiles (pad 68 / 72 -> conflict-free B-frag loads).
#define KSTRIDE 68
#define VSTRIDE 72
__global__ __launch_bounds__(256, 2) void attn_mma_kernel() {
    __shared__ float Ks[64 * KSTRIDE];
    __shared__ float Vs[64 * VSTRIDE];
    int bh   = blockIdx.y;
    int warp = threadIdx.x >> 5;
    int lane = threadIdx.x & 31;
    int gid  = lane >> 2;     // 0..7 (row group)
    int tig  = lane & 3;      // 0..3 (thread in group)
    int q0   = blockIdx.x * 128 + warp * 16;

    const float* Qb = g_q + (size_t)bh * N_TOK * HD;
    const float* Kb = g_k + (size_t)bh * N_TOK * HD;
    const float* Vb = g_v + (size_t)bh * N_TOK * HD;

    // Q fragments (already tf32-rounded in storage)
    uint32_t qa[8][4];
    #pragma unroll
    for (int dd = 0; dd < 8; dd++) {
        const float* r0 = Qb + (size_t)(q0 + gid)     * HD + dd * 8 + tig;
        const float* r1 = Qb + (size_t)(q0 + gid + 8) * HD + dd * 8 + tig;
        qa[dd][0] = __float_as_uint(r0[0]);
        qa[dd][1] = __float_as_uint(r1[0]);
        qa[dd][2] = __float_as_uint(r0[4]);
        qa[dd][3] = __float_as_uint(r1[4]);
    }

    float o[8][4];
    #pragma unroll
    for (int i = 0; i < 8; i++)
        #pragma unroll
        for (int j = 0; j < 4; j++) o[i][j] = 0.f;
    float m0 = -1e30f, m1 = -1e30f, l0 = 0.f, l1 = 0.f;
    const float SC = 0.125f * 1.4426950408889634f;   // hd^-0.5 * log2(e)

    for (int kt = 0; kt < N_TOK / 64; kt++) {
        __syncthreads();
        const float4* kg = (const float4*)(Kb + (size_t)kt * 64 * HD);
        const float4* vg = (const float4*)(Vb + (size_t)kt * 64 * HD);
        #pragma unroll
        for (int p = 0; p < 4; p++) {
            int f = threadIdx.x + p * 256;      // 0..1023 float4s
            int row = f >> 4, c4 = f & 15;
            *(float4*)&Ks[row * KSTRIDE + c4 * 4] = kg[f];
            *(float4*)&Vs[row * VSTRIDE + c4 * 4] = vg[f];
        }
        __syncthreads();

        // ---- S = Q K^T (16 x 64) ----
        float s[8][4];
        #pragma unroll
        for (int j = 0; j < 8; j++) {
            float c0 = 0, c1 = 0, c2 = 0, c3 = 0;
            const float* krow = Ks + (j * 8 + gid) * KSTRIDE;
            #pragma unroll
            for (int dd = 0; dd < 8; dd++) {
                uint32_t b0 = __float_as_uint(krow[dd * 8 + tig]);
                uint32_t b1 = __float_as_uint(krow[dd * 8 + tig + 4]);
                mma_tf32(c0, c1, c2, c3, qa[dd][0], qa[dd][1], qa[dd][2], qa[dd][3], b0, b1);
            }
            s[j][0] = c0 * SC; s[j][1] = c1 * SC; s[j][2] = c2 * SC; s[j][3] = c3 * SC;
        }

        // ---- online softmax ----
        float rmax0 = s[0][0], rmax1 = s[0][2];
        #pragma unroll
        for (int j = 0; j < 8; j++) {
            rmax0 = fmaxf(rmax0, fmaxf(s[j][0], s[j][1]));
            rmax1 = fmaxf(rmax1, fmaxf(s[j][2], s[j][3]));
        }
        rmax0 = fmaxf(rmax0, __shfl_xor_sync(0xffffffffu, rmax0, 1));
        rmax0 = fmaxf(rmax0, __shfl_xor_sync(0xffffffffu, rmax0, 2));
        rmax1 = fmaxf(rmax1, __shfl_xor_sync(0xffffffffu, rmax1, 1));
        rmax1 = fmaxf(rmax1, __shfl_xor_sync(0xffffffffu, rmax1, 2));

        float mn0 = fmaxf(m0, rmax0), mn1 = fmaxf(m1, rmax1);
        float corr0 = fast_exp2(m0 - mn0), corr1 = fast_exp2(m1 - mn1);
        m0 = mn0; m1 = mn1;
        #pragma unroll
        for (int dd = 0; dd < 8; dd++) {
            o[dd][0] *= corr0; o[dd][1] *= corr0;
            o[dd][2] *= corr1; o[dd][3] *= corr1;
        }
        float rs0 = 0.f, rs1 = 0.f;
        uint32_t pa[8][4];
        int srcA = (lane & ~3) | (tig >> 1);
        int srcB = srcA + 2;
        bool odd = (tig & 1);
        #pragma unroll
        for (int j = 0; j < 8; j++) {
            float p0 = fast_exp2(s[j][0] - mn0);
            float p1 = fast_exp2(s[j][1] - mn0);
            float p2 = fast_exp2(s[j][2] - mn1);
            float p3 = fast_exp2(s[j][3] - mn1);
            rs0 += p0 + p1; rs1 += p2 + p3;
            // D-layout -> A-layout within each quad
            float x0 = __shfl_sync(0xffffffffu, p0, srcA);
            float x1 = __shfl_sync(0xffffffffu, p1, srcA);
            float y0 = __shfl_sync(0xffffffffu, p0, srcB);
            float y1 = __shfl_sync(0xffffffffu, p1, srcB);
            float z0 = __shfl_sync(0xffffffffu, p2, srcA);
            float z1 = __shfl_sync(0xffffffffu, p3, srcA);
            float w0 = __shfl_sync(0xffffffffu, p2, srcB);
            float w1 = __shfl_sync(0xffffffffu, p3, srcB);
            pa[j][0] = to_tf32(odd ? x1 : x0);
            pa[j][1] = to_tf32(odd ? z1 : z0);
            pa[j][2] = to_tf32(odd ? y1 : y0);
            pa[j][3] = to_tf32(odd ? w1 : w0);
        }
        rs0 += __shfl_xor_sync(0xffffffffu, rs0, 1);
        rs0 += __shfl_xor_sync(0xffffffffu, rs0, 2);
        rs1 += __shfl_xor_sync(0xffffffffu, rs1, 1);
        rs1 += __shfl_xor_sync(0xffffffffu, rs1, 2);
        l0 = l0 * corr0 + rs0;
        l1 = l1 * corr1 + rs1;

        // ---- O += P V ----
        #pragma unroll
        for (int dd = 0; dd < 8; dd++) {
            float c0 = o[dd][0], c1 = o[dd][1], c2 = o[dd][2], c3 = o[dd][3];
            #pragma unroll
            for (int j = 0; j < 8; j++) {
                uint32_t b0 = __float_as_uint(Vs[(j * 8 + tig)     * VSTRIDE + dd * 8 + gid]);
                uint32_t b1 = __float_as_uint(Vs[(j * 8 + tig + 4) * VSTRIDE + dd * 8 + gid]);
                mma_tf32(c0, c1, c2, c3, pa[j][0], pa[j][1], pa[j][2], pa[j][3], b0, b1);
            }
            o[dd][0] = c0; o[dd][1] = c1; o[dd][2] = c2; o[dd][3] = c3;
        }
    }

    float inv0 = 1.f / l0, inv1 = 1.f / l1;
    float* Ob = g_o + (size_t)bh * N_TOK * HD;
    #pragma unroll
    for (int dd = 0; dd < 8; dd++) {
        float2 v0 = make_float2(o[dd][0] * inv0, o[dd][1] * inv0);
        float2 v1 = make_float2(o[dd][2] * inv1, o[dd][3] * inv1);
        *(float2*)&Ob[(size_t)(q0 + gid)     * HD + dd * 8 + 2 * tig] = v0;
        *(float2*)&Ob[(size_t)(q0 + gid + 8) * HD + dd * 8 + 2 * tig] = v1;
    }
}

// ==================== 4) proj GEMM + bias + residual ====================
__global__ __launch_bounds__(256) void proj_kernel(
    const float* __restrict__ x, const float* __restrict__ w,
    const float* __restrict__ bias, float* __restrict__ out)
{
    __shared__ float As[32][68];
    __shared__ float Bs[32][68];
    int n0 = blockIdx.x * 64;
    int m0 = blockIdx.y * 64;
    int b  = blockIdx.z;
    int tid = threadIdx.x;
    int tx = tid & 15, ty = tid >> 4;

    float acc[4][4] = {};
    for (int k0 = 0; k0 < C_DIM; k0 += 32) {
        {
            int k = tid & 31, i0 = tid >> 5;
            #pragma unroll
            for (int r = 0; r < 8; r++) {
                int i = i0 + r * 8;
                As[k][i] = w[(m0 + i) * C_DIM + k0 + k];
            }
        }
        {
            int nn = tid & 63, kk0 = tid >> 6;
            #pragma unroll
            for (int r = 0; r < 8; r++) {
                int kk = kk0 + r * 4;
                int c  = k0 + kk;
                Bs[kk][nn] = g_o[(((size_t)b * HEADS + (c >> 6)) * N_TOK + n0 + nn) * HD + (c & 63)];
            }
        }
        __syncthreads();
        #pragma unroll
        for (int k = 0; k < 32; k++) {
            float av[4], bv[4];
            *(float4*)av = *(const float4*)&As[k][ty * 4];
            *(float4*)bv = *(const float4*)&Bs[k][tx * 4];
            #pragma unroll
            for (int i = 0; i < 4; i++)
                #pragma unroll
                for (int j = 0; j < 4; j++)
                    acc[i][j] += av[i] * bv[j];
        }
        __syncthreads();
    }

    #pragma unroll
    for (int i = 0; i < 4; i++) {
        int mo = m0 + ty * 4 + i;
        float bi = bias[mo];
        size_t rowbase = (size_t)b * C_DIM * N_TOK + (size_t)mo * N_TOK + n0 + tx * 4;
        float4 res = *(const float4*)&x[rowbase];
        float4 v = make_float4(acc[i][0] + bi + res.x, acc[i][1] + bi + res.y,
                               acc[i][2] + bi + res.z, acc[i][3] + bi + res.w);
        *(float4*)&out[rowbase] = v;
    }
}

// ==================== launch ====================
extern "C" void kernel_launch(void* const* d_in, const int* in_sizes, int n_in,
                              void* d_out, int out_size) {
    const float* x      = (const float*)d_in[0];
    const float* gamma  = (const float*)d_in[1];
    const float* beta   = (const float*)d_in[2];
    const float* w_qkv  = (const float*)d_in[3];
    const float* b_qkv  = (const float*)d_in[4];
    const float* w_proj = (const float*)d_in[5];
    const float* b_proj = (const float*)d_in[6];
    float* out = (float*)d_out;

    gn_stats_kernel<<<BATCH * GROUPS, 512>>>(x);
    qkv_kernel<<<dim3(N_TOK / 64, (3 * C_DIM) / 64, BATCH), 256>>>(x, gamma, beta, w_qkv, b_qkv);
    attn_mma_kernel<<<dim3(N_TOK / 128, BATCH * HEADS), 256>>>();
    proj_kernel<<<dim3(N_TOK / 64, C_DIM / 64, BATCH), 256>>>(x, w_proj, b_proj, out);
}

// round 3
// speedup vs baseline: 12.4673x; 2.4181x over previous
#include <cuda_runtime.h>
#include <cuda_fp16.h>
#include <math.h>
#include <stdint.h>

#define BATCH   2
#define C_DIM   256
#define N_TOK   4096
#define HEADS   4
#define HD      64
#define GROUPS  8
#define GCNT    ((C_DIM / GROUPS) * N_TOK)      // 131072 per (b,g)
#define GN_SPLIT 8

// -------- scratch --------
__device__ float  g_stats[BATCH * GROUPS * 2];               // mean, rstd
__device__ float2 g_part[BATCH * GROUPS * GN_SPLIT];
__device__ __half g_q [BATCH * HEADS * N_TOK * HD];          // [bh][n][d], pre-scaled
__device__ __half g_k [BATCH * HEADS * N_TOK * HD];          // [bh][n][d]
__device__ __half g_vt[BATCH * HEADS * HD * N_TOK];          // [bh][d][n]  (transposed!)
__device__ float  g_o [BATCH * C_DIM * N_TOK];               // [b][c][n] channel-major

__device__ __forceinline__ float fast_exp2(float x) {
    float r; asm("ex2.approx.ftz.f32 %0, %1;" : "=f"(r) : "f"(x)); return r;
}
__device__ __forceinline__ float tf32r(float x) {
    uint32_t r; asm("cvt.rna.tf32.f32 %0, %1;" : "=r"(r) : "f"(x));
    return __uint_as_float(r);
}
__device__ __forceinline__ uint32_t pack_h2(float a, float b) {
    __half2 h = __floats2half2_rn(a, b); return *(uint32_t*)&h;
}
__device__ __forceinline__ void mma_tf32(float* c, const uint32_t* a, uint32_t b0, uint32_t b1) {
    asm volatile(
        "mma.sync.aligned.m16n8k8.row.col.f32.tf32.tf32.f32 "
        "{%0,%1,%2,%3}, {%4,%5,%6,%7}, {%8,%9}, {%0,%1,%2,%3};"
        : "+f"(c[0]), "+f"(c[1]), "+f"(c[2]), "+f"(c[3])
        : "r"(a[0]), "r"(a[1]), "r"(a[2]), "r"(a[3]), "r"(b0), "r"(b1));
}
__device__ __forceinline__ void mma_f16(float* c, const uint32_t* a, uint32_t b0, uint32_t b1) {
    asm volatile(
        "mma.sync.aligned.m16n8k16.row.col.f32.f16.f16.f32 "
        "{%0,%1,%2,%3}, {%4,%5,%6,%7}, {%8,%9}, {%0,%1,%2,%3};"
        : "+f"(c[0]), "+f"(c[1]), "+f"(c[2]), "+f"(c[3])
        : "r"(a[0]), "r"(a[1]), "r"(a[2]), "r"(a[3]), "r"(b0), "r"(b1));
}

// ==================== 1) GroupNorm stats: partial + finalize ====================
__global__ __launch_bounds__(256) void gn_part_kernel(const float* __restrict__ x) {
    int bg = blockIdx.x >> 3, part = blockIdx.x & 7;
    const float4* p = (const float4*)(x + (size_t)bg * GCNT + (size_t)part * (GCNT / GN_SPLIT));
    const int n4 = GCNT / GN_SPLIT / 4;     // 4096
    float s = 0.f, ss = 0.f;
    for (int i = threadIdx.x; i < n4; i += 256) {
        float4 v = p[i];
        s  += v.x + v.y + v.z + v.w;
        ss += v.x * v.x + v.y * v.y + v.z * v.z + v.w * v.w;
    }
    #pragma unroll
    for (int o = 16; o > 0; o >>= 1) {
        s  += __shfl_xor_sync(0xffffffffu, s, o);
        ss += __shfl_xor_sync(0xffffffffu, ss, o);
    }
    __shared__ float sh1[8], sh2[8];
    int w = threadIdx.x >> 5, lane = threadIdx.x & 31;
    if (lane == 0) { sh1[w] = s; sh2[w] = ss; }
    __syncthreads();
    if (threadIdx.x == 0) {
        float t1 = 0.f, t2 = 0.f;
        #pragma unroll
        for (int i = 0; i < 8; i++) { t1 += sh1[i]; t2 += sh2[i]; }
        g_part[blockIdx.x] = make_float2(t1, t2);
    }
}
__global__ void gn_fin_kernel() {
    int t = threadIdx.x;
    if (t < BATCH * GROUPS) {
        float s = 0.f, ss = 0.f;
        #pragma unroll
        for (int i = 0; i < GN_SPLIT; i++) {
            float2 v = g_part[t * GN_SPLIT + i];
            s += v.x; ss += v.y;
        }
        float mean = s * (1.f / GCNT);
        float var  = ss * (1.f / GCNT) - mean * mean;
        g_stats[t * 2]     = mean;
        g_stats[t * 2 + 1] = rsqrtf(var + 1e-5f);
    }
}

// ==================== 2) QKV: TF32 MMA GEMM + GN fused ====================
// Block: 64 (out-ch) x 128 (tokens), K=256. 8 warps (2m x 4n), warp 32x32.
__global__ __launch_bounds__(256) void qkv_mma_kernel(
    const float* __restrict__ x, const float* __restrict__ gamma,
    const float* __restrict__ beta, const float* __restrict__ w,
    const float* __restrict__ bias)
{
    __shared__ float coA[C_DIM], coB[C_DIM];
    __shared__ float As[64 * 36];
    __shared__ float Bs[32 * 136];
    int n0 = blockIdx.x * 128, m0 = blockIdx.y * 64, b = blockIdx.z;
    int tid = threadIdx.x;
    int warp = tid >> 5, lane = tid & 31, gid = lane >> 2, tig = lane & 3;
    int wm = (warp & 1) * 32, wn = (warp >> 1) * 32;

    {
        int c = tid;
        int sg = (b * GROUPS + (c >> 5)) * 2;
        float mean = g_stats[sg], rstd = g_stats[sg + 1];
        float a = rstd * gamma[c];
        coA[c] = a; coB[c] = beta[c] - mean * a;
    }

    float acc[2][4][4] = {};
    const float* xb = x + (size_t)b * C_DIM * N_TOK;

    for (int k0 = 0; k0 < C_DIM; k0 += 32) {
        __syncthreads();
        #pragma unroll
        for (int i = 0; i < 2; i++) {
            int f = tid + i * 256;
            int m = f >> 3, k4 = (f & 7) * 4;
            float4 wv = *(const float4*)&w[(size_t)(m0 + m) * C_DIM + k0 + k4];
            wv.x = tf32r(wv.x); wv.y = tf32r(wv.y); wv.z = tf32r(wv.z); wv.w = tf32r(wv.w);
            *(float4*)&As[m * 36 + k4] = wv;
        }
        #pragma unroll
        for (int i = 0; i < 4; i++) {
            int f = tid + i * 256;
            int kk = f >> 5, n4 = (f & 31) * 4;
            int c = k0 + kk;
            float4 xv = *(const float4*)&xb[(size_t)c * N_TOK + n0 + n4];
            float a = coA[c], bb = coB[c];
            float4 r = make_float4(tf32r(xv.x * a + bb), tf32r(xv.y * a + bb),
                                   tf32r(xv.z * a + bb), tf32r(xv.w * a + bb));
            *(float4*)&Bs[kk * 136 + n4] = r;
        }
        __syncthreads();
        #pragma unroll
        for (int kk = 0; kk < 4; kk++) {
            int k = kk * 8;
            uint32_t af[2][4];
            #pragma unroll
            for (int mt = 0; mt < 2; mt++) {
                const float* ap = &As[(wm + mt * 16 + gid) * 36 + k + tig];
                af[mt][0] = __float_as_uint(ap[0]);
                af[mt][1] = __float_as_uint(ap[8 * 36]);
                af[mt][2] = __float_as_uint(ap[4]);
                af[mt][3] = __float_as_uint(ap[8 * 36 + 4]);
            }
            #pragma unroll
            for (int nt = 0; nt < 4; nt++) {
                uint32_t b0 = __float_as_uint(Bs[(k + tig) * 136 + wn + nt * 8 + gid]);
                uint32_t b1 = __float_as_uint(Bs[(k + tig + 4) * 136 + wn + nt * 8 + gid]);
                mma_tf32(acc[0][nt], af[0], b0, b1);
                mma_tf32(acc[1][nt], af[1], b0, b1);
            }
        }
    }

    // epilogue: route to q/k (fp16 [bh][n][d]) or v-transposed (fp16 [bh][d][n])
    const float QSCALE = 0.125f * 1.4426950408889634f;
    int which = m0 >> 8;                 // 0:q 1:k 2:v
    int h     = (m0 >> 6) & 3;
    int bh    = b * HEADS + h;
    #pragma unroll
    for (int mt = 0; mt < 2; mt++) {
        int d  = wm + mt * 16 + gid;     // local out-ch (== head dim since m0%64==0)
        float bi0 = bias[m0 + d], bi1 = bias[m0 + d + 8];
        #pragma unroll
        for (int nt = 0; nt < 4; nt++) {
            int n = n0 + wn + nt * 8 + 2 * tig;
            float v0 = acc[mt][nt][0] + bi0, v1 = acc[mt][nt][1] + bi0;
            float v2 = acc[mt][nt][2] + bi1, v3 = acc[mt][nt][3] + bi1;
            if (which == 0) {
                v0 *= QSCALE; v1 *= QSCALE; v2 *= QSCALE; v3 *= QSCALE;
                __half* q = g_q + ((size_t)bh * N_TOK) * HD;
                q[(size_t)n * HD + d]           = __float2half_rn(v0);
                q[(size_t)(n + 1) * HD + d]     = __float2half_rn(v1);
                q[(size_t)n * HD + d + 8]       = __float2half_rn(v2);
                q[(size_t)(n + 1) * HD + d + 8] = __float2half_rn(v3);
            } else if (which == 1) {
                __half* kq = g_k + ((size_t)bh * N_TOK) * HD;
                kq[(size_t)n * HD + d]           = __float2half_rn(v0);
                kq[(size_t)(n + 1) * HD + d]     = __float2half_rn(v1);
                kq[(size_t)n * HD + d + 8]       = __float2half_rn(v2);
                kq[(size_t)(n + 1) * HD + d + 8] = __float2half_rn(v3);
            } else {
                __half* vt = g_vt + ((size_t)bh * HD) * N_TOK;
                *(__half2*)&vt[(size_t)d * N_TOK + n]       = *(__half2*)&(__half2&)*(uint32_t[]){pack_h2(v0, v1)};
                *(__half2*)&vt[(size_t)(d + 8) * N_TOK + n] = *(__half2*)&(__half2&)*(uint32_t[]){pack_h2(v2, v3)};
            }
        }
    }
}

// ==================== 3) Flash attention (fp16 m16n8k16) ====================
#define KS 72
__global__ __launch_bounds__(256, 2) void attn_kernel() {
    __shared__ __half Ks[64 * KS];
    __shared__ __half Vt[64 * KS];
    int bh   = blockIdx.y;
    int tid  = threadIdx.x;
    int warp = tid >> 5, lane = tid & 31, gid = lane >> 2, tig = lane & 3;
    int q0   = blockIdx.x * 128 + warp * 16;

    const __half* Qb = g_q  + (size_t)bh * N_TOK * HD;
    const __half* Kb = g_k  + (size_t)bh * N_TOK * HD;
    const __half* Vb = g_vt + (size_t)bh * HD * N_TOK;

    uint32_t qa[4][4];
    #pragma unroll
    for (int dd = 0; dd < 4; dd++) {
        const __half* r0 = Qb + (size_t)(q0 + gid)     * HD + dd * 16 + 2 * tig;
        const __half* r1 = Qb + (size_t)(q0 + gid + 8) * HD + dd * 16 + 2 * tig;
        qa[dd][0] = *(const uint32_t*)r0;
        qa[dd][1] = *(const uint32_t*)r1;
        qa[dd][2] = *(const uint32_t*)(r0 + 8);
        qa[dd][3] = *(const uint32_t*)(r1 + 8);
    }

    float o[8][4];
    #pragma unroll
    for (int i = 0; i < 8; i++) { o[i][0] = o[i][1] = o[i][2] = o[i][3] = 0.f; }
    float m0v = -1e30f, m1v = -1e30f, l0 = 0.f, l1 = 0.f;

    for (int kt = 0; kt < N_TOK / 64; kt++) {
        __syncthreads();
        #pragma unroll
        for (int i = 0; i < 2; i++) {
            int f = tid + i * 256;
            int row = f >> 3, seg = (f & 7) * 8;
            *(uint4*)&Ks[row * KS + seg] = *(const uint4*)&Kb[(size_t)(kt * 64 + row) * HD + seg];
            *(uint4*)&Vt[row * KS + seg] = *(const uint4*)&Vb[(size_t)row * N_TOK + kt * 64 + seg];
        }
        __syncthreads();

        // S = Q K^T  (16 x 64)
        float s[8][4];
        #pragma unroll
        for (int j = 0; j < 8; j++) {
            s[j][0] = s[j][1] = s[j][2] = s[j][3] = 0.f;
            const __half* kr = &Ks[(j * 8 + gid) * KS + 2 * tig];
            #pragma unroll
            for (int dd = 0; dd < 4; dd++) {
                uint32_t b0 = *(const uint32_t*)(kr + dd * 16);
                uint32_t b1 = *(const uint32_t*)(kr + dd * 16 + 8);
                mma_f16(s[j], qa[dd], b0, b1);
            }
        }

        // online softmax (scale already folded into Q)
        float rmax0 = s[0][0], rmax1 = s[0][2];
        #pragma unroll
        for (int j = 0; j < 8; j++) {
            rmax0 = fmaxf(rmax0, fmaxf(s[j][0], s[j][1]));
            rmax1 = fmaxf(rmax1, fmaxf(s[j][2], s[j][3]));
        }
        rmax0 = fmaxf(rmax0, __shfl_xor_sync(0xffffffffu, rmax0, 1));
        rmax0 = fmaxf(rmax0, __shfl_xor_sync(0xffffffffu, rmax0, 2));
        rmax1 = fmaxf(rmax1, __shfl_xor_sync(0xffffffffu, rmax1, 1));
        rmax1 = fmaxf(rmax1, __shfl_xor_sync(0xffffffffu, rmax1, 2));
        float mn0 = fmaxf(m0v, rmax0), mn1 = fmaxf(m1v, rmax1);
        float corr0 = fast_exp2(m0v - mn0), corr1 = fast_exp2(m1v - mn1);
        m0v = mn0; m1v = mn1;
        #pragma unroll
        for (int dd = 0; dd < 8; dd++) {
            o[dd][0] *= corr0; o[dd][1] *= corr0;
            o[dd][2] *= corr1; o[dd][3] *= corr1;
        }

        float rs0 = 0.f, rs1 = 0.f;
        uint32_t pa[4][4];
        #pragma unroll
        for (int j = 0; j < 8; j++) {
            float p0 = fast_exp2(s[j][0] - mn0);
            float p1 = fast_exp2(s[j][1] - mn0);
            float p2 = fast_exp2(s[j][2] - mn1);
            float p3 = fast_exp2(s[j][3] - mn1);
            rs0 += p0 + p1; rs1 += p2 + p3;
            int jj = j >> 1;
            if ((j & 1) == 0) { pa[jj][0] = pack_h2(p0, p1); pa[jj][1] = pack_h2(p2, p3); }
            else              { pa[jj][2] = pack_h2(p0, p1); pa[jj][3] = pack_h2(p2, p3); }
        }
        rs0 += __shfl_xor_sync(0xffffffffu, rs0, 1);
        rs0 += __shfl_xor_sync(0xffffffffu, rs0, 2);
        rs1 += __shfl_xor_sync(0xffffffffu, rs1, 1);
        rs1 += __shfl_xor_sync(0xffffffffu, rs1, 2);
        l0 = l0 * corr0 + rs0;
        l1 = l1 * corr1 + rs1;

        // O += P V   (P fragments already in A layout — no shuffles)
        #pragma unroll
        for (int dd = 0; dd < 8; dd++) {
            const __half* vr = &Vt[(dd * 8 + gid) * KS + 2 * tig];
            #pragma unroll
            for (int jj = 0; jj < 4; jj++) {
                uint32_t b0 = *(const uint32_t*)(vr + jj * 16);
                uint32_t b1 = *(const uint32_t*)(vr + jj * 16 + 8);
                mma_f16(o[dd], pa[jj], b0, b1);
            }
        }
    }

    float inv0 = 1.f / l0, inv1 = 1.f / l1;
    float* Ob = g_o + (size_t)bh * HD * N_TOK;     // [c][n] within (b), c = h*64+d
    #pragma unroll
    for (int dd = 0; dd < 8; dd++) {
        int d = dd * 8 + 2 * tig;
        Ob[(size_t)d * N_TOK + q0 + gid]           = o[dd][0] * inv0;
        Ob[(size_t)(d + 1) * N_TOK + q0 + gid]     = o[dd][1] * inv0;
        Ob[(size_t)d * N_TOK + q0 + gid + 8]       = o[dd][2] * inv1;
        Ob[(size_t)(d + 1) * N_TOK + q0 + gid + 8] = o[dd][3] * inv1;
    }
}

// ==================== 4) proj: TF32 MMA GEMM + bias + residual ====================
__global__ __launch_bounds__(256) void proj_mma_kernel(
    const float* __restrict__ x, const float* __restrict__ w,
    const float* __restrict__ bias, float* __restrict__ out)
{
    __shared__ float As[64 * 36];
    __shared__ float Bs[32 * 136];
    int n0 = blockIdx.x * 128, m0 = blockIdx.y * 64, b = blockIdx.z;
    int tid = threadIdx.x;
    int warp = tid >> 5, lane = tid & 31, gid = lane >> 2, tig = lane & 3;
    int wm = (warp & 1) * 32, wn = (warp >> 1) * 32;

    float acc[2][4][4] = {};
    const float* ob = g_o + (size_t)b * C_DIM * N_TOK;

    for (int k0 = 0; k0 < C_DIM; k0 += 32) {
        __syncthreads();
        #pragma unroll
        for (int i = 0; i < 2; i++) {
            int f = tid + i * 256;
            int m = f >> 3, k4 = (f & 7) * 4;
            float4 wv = *(const float4*)&w[(size_t)(m0 + m) * C_DIM + k0 + k4];
            wv.x = tf32r(wv.x); wv.y = tf32r(wv.y); wv.z = tf32r(wv.z); wv.w = tf32r(wv.w);
            *(float4*)&As[m * 36 + k4] = wv;
        }
        #pragma unroll
        for (int i = 0; i < 4; i++) {
            int f = tid + i * 256;
            int kk = f >> 5, n4 = (f & 31) * 4;
            float4 xv = *(const float4*)&ob[(size_t)(k0 + kk) * N_TOK + n0 + n4];
            float4 r = make_float4(tf32r(xv.x), tf32r(xv.y), tf32r(xv.z), tf32r(xv.w));
            *(float4*)&Bs[kk * 136 + n4] = r;
        }
        __syncthreads();
        #pragma unroll
        for (int kk = 0; kk < 4; kk++) {
            int k = kk * 8;
            uint32_t af[2][4];
            #pragma unroll
            for (int mt = 0; mt < 2; mt++) {
                const float* ap = &As[(wm + mt * 16 + gid) * 36 + k + tig];
                af[mt][0] = __float_as_uint(ap[0]);
                af[mt][1] = __float_as_uint(ap[8 * 36]);
                af[mt][2] = __float_as_uint(ap[4]);
                af[mt][3] = __float_as_uint(ap[8 * 36 + 4]);
            }
            #pragma unroll
            for (int nt = 0; nt < 4; nt++) {
                uint32_t b0 = __float_as_uint(Bs[(k + tig) * 136 + wn + nt * 8 + gid]);
                uint32_t b1 = __float_as_uint(Bs[(k + tig + 4) * 136 + wn + nt * 8 + gid]);
                mma_tf32(acc[0][nt], af[0], b0, b1);
                mma_tf32(acc[1][nt], af[1], b0, b1);
            }
        }
    }

    #pragma unroll
    for (int mt = 0; mt < 2; mt++) {
        int m = m0 + wm + mt * 16 + gid;
        float bi0 = bias[m], bi1 = bias[m + 8];
        #pragma unroll
        for (int nt = 0; nt < 4; nt++) {
            int n = n0 + wn + nt * 8 + 2 * tig;
            size_t a0 = (size_t)(b * C_DIM + m) * N_TOK + n;
            size_t a1 = (size_t)(b * C_DIM + m + 8) * N_TOK + n;
            float2 r0 = *(const float2*)&x[a0];
            float2 r1 = *(const float2*)&x[a1];
            float2 v0 = make_float2(acc[mt][nt][0] + bi0 + r0.x, acc[mt][nt][1] + bi0 + r0.y);
            float2 v1 = make_float2(acc[mt][nt][2] + bi1 + r1.x, acc[mt][nt][3] + bi1 + r1.y);
            *(float2*)&out[a0] = v0;
            *(float2*)&out[a1] = v1;
        }
    }
}

// ==================== launch ====================
extern "C" void kernel_launch(void* const* d_in, const int* in_sizes, int n_in,
                              void* d_out, int out_size) {
    const float* x      = (const float*)d_in[0];
    const float* gamma  = (const float*)d_in[1];
    const float* beta   = (const float*)d_in[2];
    const float* w_qkv  = (const float*)d_in[3];
    const float* b_qkv  = (const float*)d_in[4];
    const float* w_proj = (const float*)d_in[5];
    const float* b_proj = (const float*)d_in[6];
    float* out = (float*)d_out;

    gn_part_kernel<<<BATCH * GROUPS * GN_SPLIT, 256>>>(x);
    gn_fin_kernel<<<1, 32>>>();
    qkv_mma_kernel<<<dim3(N_TOK / 128, (3 * C_DIM) / 64, BATCH), 256>>>(x, gamma, beta, w_qkv, b_qkv);
    attn_kernel<<<dim3(N_TOK / 128, BATCH * HEADS), 256>>>();
    proj_mma_kernel<<<dim3(N_TOK / 128, C_DIM / 64, BATCH), 256>>>(x, w_proj, b_proj, out);
}

// round 4
// speedup vs baseline: 12.7368x; 1.0216x over previous
#include <cuda_runtime.h>
#include <cuda_fp16.h>
#include <math.h>
#include <stdint.h>

#define BATCH   2
#define C_DIM   256
#define N_TOK   4096
#define HEADS   4
#define HD      64
#define GROUPS  8
#define GCNT    ((C_DIM / GROUPS) * N_TOK)      // 131072 per (b,g)
#define GN_SPLIT 8

// -------- scratch --------
__device__ float  g_stats[BATCH * GROUPS * 2];               // mean, rstd
__device__ float2 g_part[BATCH * GROUPS * GN_SPLIT];
__device__ __half g_q [BATCH * HEADS * N_TOK * HD];          // [bh][n][d], pre-scaled
__device__ __half g_k [BATCH * HEADS * N_TOK * HD];          // [bh][n][d]
__device__ __half g_vt[BATCH * HEADS * HD * N_TOK];          // [bh][d][n]  (transposed!)
__device__ float  g_o [BATCH * C_DIM * N_TOK];               // [b][c][n] channel-major

__device__ __forceinline__ float fast_exp2(float x) {
    float r; asm("ex2.approx.ftz.f32 %0, %1;" : "=f"(r) : "f"(x)); return r;
}
__device__ __forceinline__ float tf32r(float x) {
    uint32_t r; asm("cvt.rna.tf32.f32 %0, %1;" : "=r"(r) : "f"(x));
    return __uint_as_float(r);
}
__device__ __forceinline__ uint32_t pack_h2(float a, float b) {
    __half2 h = __floats2half2_rn(a, b); return *(uint32_t*)&h;
}
__device__ __forceinline__ void mma_tf32(float* c, const uint32_t* a, uint32_t b0, uint32_t b1) {
    asm volatile(
        "mma.sync.aligned.m16n8k8.row.col.f32.tf32.tf32.f32 "
        "{%0,%1,%2,%3}, {%4,%5,%6,%7}, {%8,%9}, {%0,%1,%2,%3};"
        : "+f"(c[0]), "+f"(c[1]), "+f"(c[2]), "+f"(c[3])
        : "r"(a[0]), "r"(a[1]), "r"(a[2]), "r"(a[3]), "r"(b0), "r"(b1));
}
__device__ __forceinline__ void mma_f16(float* c, const uint32_t* a, uint32_t b0, uint32_t b1) {
    asm volatile(
        "mma.sync.aligned.m16n8k16.row.col.f32.f16.f16.f32 "
        "{%0,%1,%2,%3}, {%4,%5,%6,%7}, {%8,%9}, {%0,%1,%2,%3};"
        : "+f"(c[0]), "+f"(c[1]), "+f"(c[2]), "+f"(c[3])
        : "r"(a[0]), "r"(a[1]), "r"(a[2]), "r"(a[3]), "r"(b0), "r"(b1));
}

// ==================== 1) GroupNorm stats: partial + finalize ====================
__global__ __launch_bounds__(256) void gn_part_kernel(const float* __restrict__ x) {
    int bg = blockIdx.x >> 3, part = blockIdx.x & 7;
    const float4* p = (const float4*)(x + (size_t)bg * GCNT + (size_t)part * (GCNT / GN_SPLIT));
    const int n4 = GCNT / GN_SPLIT / 4;     // 4096
    float s = 0.f, ss = 0.f;
    for (int i = threadIdx.x; i < n4; i += 256) {
        float4 v = p[i];
        s  += v.x + v.y + v.z + v.w;
        ss += v.x * v.x + v.y * v.y + v.z * v.z + v.w * v.w;
    }
    #pragma unroll
    for (int o = 16; o > 0; o >>= 1) {
        s  += __shfl_xor_sync(0xffffffffu, s, o);
        ss += __shfl_xor_sync(0xffffffffu, ss, o);
    }
    __shared__ float sh1[8], sh2[8];
    int w = threadIdx.x >> 5, lane = threadIdx.x & 31;
    if (lane == 0) { sh1[w] = s; sh2[w] = ss; }
    __syncthreads();
    if (threadIdx.x == 0) {
        float t1 = 0.f, t2 = 0.f;
        #pragma unroll
        for (int i = 0; i < 8; i++) { t1 += sh1[i]; t2 += sh2[i]; }
        g_part[blockIdx.x] = make_float2(t1, t2);
    }
}
__global__ void gn_fin_kernel() {
    int t = threadIdx.x;
    if (t < BATCH * GROUPS) {
        float s = 0.f, ss = 0.f;
        #pragma unroll
        for (int i = 0; i < GN_SPLIT; i++) {
            float2 v = g_part[t * GN_SPLIT + i];
            s += v.x; ss += v.y;
        }
        float mean = s * (1.f / GCNT);
        float var  = ss * (1.f / GCNT) - mean * mean;
        g_stats[t * 2]     = mean;
        g_stats[t * 2 + 1] = rsqrtf(var + 1e-5f);
    }
}

// ==================== 2) QKV: TF32 MMA GEMM + GN fused ====================
__global__ __launch_bounds__(256) void qkv_mma_kernel(
    const float* __restrict__ x, const float* __restrict__ gamma,
    const float* __restrict__ beta, const float* __restrict__ w,
    const float* __restrict__ bias)
{
    __shared__ float coA[C_DIM], coB[C_DIM];
    __shared__ float As[64 * 36];
    __shared__ float Bs[32 * 136];
    int n0 = blockIdx.x * 128, m0 = blockIdx.y * 64, b = blockIdx.z;
    int tid = threadIdx.x;
    int warp = tid >> 5, lane = tid & 31, gid = lane >> 2, tig = lane & 3;
    int wm = (warp & 1) * 32, wn = (warp >> 1) * 32;

    {
        int c = tid;
        int sg = (b * GROUPS + (c >> 5)) * 2;
        float mean = g_stats[sg], rstd = g_stats[sg + 1];
        float a = rstd * gamma[c];
        coA[c] = a; coB[c] = beta[c] - mean * a;
    }

    float acc[2][4][4] = {};
    const float* xb = x + (size_t)b * C_DIM * N_TOK;

    for (int k0 = 0; k0 < C_DIM; k0 += 32) {
        __syncthreads();
        #pragma unroll
        for (int i = 0; i < 2; i++) {
            int f = tid + i * 256;
            int m = f >> 3, k4 = (f & 7) * 4;
            float4 wv = *(const float4*)&w[(size_t)(m0 + m) * C_DIM + k0 + k4];
            wv.x = tf32r(wv.x); wv.y = tf32r(wv.y); wv.z = tf32r(wv.z); wv.w = tf32r(wv.w);
            *(float4*)&As[m * 36 + k4] = wv;
        }
        #pragma unroll
        for (int i = 0; i < 4; i++) {
            int f = tid + i * 256;
            int kk = f >> 5, n4 = (f & 31) * 4;
            int c = k0 + kk;
            float4 xv = *(const float4*)&xb[(size_t)c * N_TOK + n0 + n4];
            float a = coA[c], bb = coB[c];
            float4 r = make_float4(tf32r(xv.x * a + bb), tf32r(xv.y * a + bb),
                                   tf32r(xv.z * a + bb), tf32r(xv.w * a + bb));
            *(float4*)&Bs[kk * 136 + n4] = r;
        }
        __syncthreads();
        #pragma unroll
        for (int kk = 0; kk < 4; kk++) {
            int k = kk * 8;
            uint32_t af[2][4];
            #pragma unroll
            for (int mt = 0; mt < 2; mt++) {
                const float* ap = &As[(wm + mt * 16 + gid) * 36 + k + tig];
                af[mt][0] = __float_as_uint(ap[0]);
                af[mt][1] = __float_as_uint(ap[8 * 36]);
                af[mt][2] = __float_as_uint(ap[4]);
                af[mt][3] = __float_as_uint(ap[8 * 36 + 4]);
            }
            #pragma unroll
            for (int nt = 0; nt < 4; nt++) {
                uint32_t b0 = __float_as_uint(Bs[(k + tig) * 136 + wn + nt * 8 + gid]);
                uint32_t b1 = __float_as_uint(Bs[(k + tig + 4) * 136 + wn + nt * 8 + gid]);
                mma_tf32(acc[0][nt], af[0], b0, b1);
                mma_tf32(acc[1][nt], af[1], b0, b1);
            }
        }
    }

    const float QSCALE = 0.125f * 1.4426950408889634f;
    int which = m0 >> 8;                 // 0:q 1:k 2:v
    int h     = (m0 >> 6) & 3;
    int bh    = b * HEADS + h;
    #pragma unroll
    for (int mt = 0; mt < 2; mt++) {
        int d  = wm + mt * 16 + gid;
        float bi0 = bias[m0 + d], bi1 = bias[m0 + d + 8];
        #pragma unroll
        for (int nt = 0; nt < 4; nt++) {
            int n = n0 + wn + nt * 8 + 2 * tig;
            float v0 = acc[mt][nt][0] + bi0, v1 = acc[mt][nt][1] + bi0;
            float v2 = acc[mt][nt][2] + bi1, v3 = acc[mt][nt][3] + bi1;
            if (which == 0) {
                v0 *= QSCALE; v1 *= QSCALE; v2 *= QSCALE; v3 *= QSCALE;
                __half* q = g_q + ((size_t)bh * N_TOK) * HD;
                q[(size_t)n * HD + d]           = __float2half_rn(v0);
                q[(size_t)(n + 1) * HD + d]     = __float2half_rn(v1);
                q[(size_t)n * HD + d + 8]       = __float2half_rn(v2);
                q[(size_t)(n + 1) * HD + d + 8] = __float2half_rn(v3);
            } else if (which == 1) {
                __half* kq = g_k + ((size_t)bh * N_TOK) * HD;
                kq[(size_t)n * HD + d]           = __float2half_rn(v0);
                kq[(size_t)(n + 1) * HD + d]     = __float2half_rn(v1);
                kq[(size_t)n * HD + d + 8]       = __float2half_rn(v2);
                kq[(size_t)(n + 1) * HD + d + 8] = __float2half_rn(v3);
            } else {
                __half* vt = g_vt + ((size_t)bh * HD) * N_TOK;
                uint32_t u0 = pack_h2(v0, v1), u1 = pack_h2(v2, v3);
                *(uint32_t*)&vt[(size_t)d * N_TOK + n]       = u0;
                *(uint32_t*)&vt[(size_t)(d + 8) * N_TOK + n] = u1;
            }
        }
    }
}

// ==================== 3) Flash attention (fp16 mma, cp.async double-buffer) ====================
#define KS 72
__global__ __launch_bounds__(256, 2) void attn_kernel() {
    __shared__ __half Ks[2][64 * KS];
    __shared__ __half Vt[2][64 * KS];
    int bh   = blockIdx.y;
    int tid  = threadIdx.x;
    int warp = tid >> 5, lane = tid & 31, gid = lane >> 2, tig = lane & 3;
    int q0   = blockIdx.x * 128 + warp * 16;

    const __half* Qb = g_q  + (size_t)bh * N_TOK * HD;
    const __half* Kb = g_k  + (size_t)bh * N_TOK * HD;
    const __half* Vb = g_vt + (size_t)bh * HD * N_TOK;

    // per-thread source/dest for the 2 K rows + 2 V rows it copies (16B each)
    int f0 = tid, f1 = tid + 256;
    int r0 = f0 >> 3, s0 = (f0 & 7) * 8;
    int r1 = f1 >> 3, s1 = (f1 & 7) * 8;

    auto load_tile = [&](int kt, int buf) {
        uint32_t kd0 = (uint32_t)__cvta_generic_to_shared(&Ks[buf][r0 * KS + s0]);
        uint32_t kd1 = (uint32_t)__cvta_generic_to_shared(&Ks[buf][r1 * KS + s1]);
        uint32_t vd0 = (uint32_t)__cvta_generic_to_shared(&Vt[buf][r0 * KS + s0]);
        uint32_t vd1 = (uint32_t)__cvta_generic_to_shared(&Vt[buf][r1 * KS + s1]);
        const __half* ks0 = &Kb[(size_t)(kt * 64 + r0) * HD + s0];
        const __half* ks1 = &Kb[(size_t)(kt * 64 + r1) * HD + s1];
        const __half* vs0 = &Vb[(size_t)r0 * N_TOK + kt * 64 + s0];
        const __half* vs1 = &Vb[(size_t)r1 * N_TOK + kt * 64 + s1];
        asm volatile("cp.async.cg.shared.global [%0], [%1], 16;" :: "r"(kd0), "l"(ks0));
        asm volatile("cp.async.cg.shared.global [%0], [%1], 16;" :: "r"(kd1), "l"(ks1));
        asm volatile("cp.async.cg.shared.global [%0], [%1], 16;" :: "r"(vd0), "l"(vs0));
        asm volatile("cp.async.cg.shared.global [%0], [%1], 16;" :: "r"(vd1), "l"(vs1));
        asm volatile("cp.async.commit_group;");
    };

    uint32_t qa[4][4];
    #pragma unroll
    for (int dd = 0; dd < 4; dd++) {
        const __half* rq0 = Qb + (size_t)(q0 + gid)     * HD + dd * 16 + 2 * tig;
        const __half* rq1 = Qb + (size_t)(q0 + gid + 8) * HD + dd * 16 + 2 * tig;
        qa[dd][0] = *(const uint32_t*)rq0;
        qa[dd][1] = *(const uint32_t*)rq1;
        qa[dd][2] = *(const uint32_t*)(rq0 + 8);
        qa[dd][3] = *(const uint32_t*)(rq1 + 8);
    }

    float o[8][4];
    #pragma unroll
    for (int i = 0; i < 8; i++) { o[i][0] = o[i][1] = o[i][2] = o[i][3] = 0.f; }
    float m0v = -1e30f, m1v = -1e30f, l0 = 0.f, l1 = 0.f;

    load_tile(0, 0);
    int buf = 0;

    for (int kt = 0; kt < N_TOK / 64; kt++) {
        asm volatile("cp.async.wait_group 0;" ::: "memory");
        __syncthreads();
        if (kt + 1 < N_TOK / 64) load_tile(kt + 1, buf ^ 1);

        const __half* Kc = Ks[buf];
        const __half* Vc = Vt[buf];

        // S = Q K^T  (16 x 64)
        float s[8][4];
        #pragma unroll
        for (int j = 0; j < 8; j++) {
            s[j][0] = s[j][1] = s[j][2] = s[j][3] = 0.f;
            const __half* kr = &Kc[(j * 8 + gid) * KS + 2 * tig];
            #pragma unroll
            for (int dd = 0; dd < 4; dd++) {
                uint32_t b0 = *(const uint32_t*)(kr + dd * 16);
                uint32_t b1 = *(const uint32_t*)(kr + dd * 16 + 8);
                mma_f16(s[j], qa[dd], b0, b1);
            }
        }

        // online softmax (scale already folded into Q)
        float rmax0 = s[0][0], rmax1 = s[0][2];
        #pragma unroll
        for (int j = 0; j < 8; j++) {
            rmax0 = fmaxf(rmax0, fmaxf(s[j][0], s[j][1]));
            rmax1 = fmaxf(rmax1, fmaxf(s[j][2], s[j][3]));
        }
        rmax0 = fmaxf(rmax0, __shfl_xor_sync(0xffffffffu, rmax0, 1));
        rmax0 = fmaxf(rmax0, __shfl_xor_sync(0xffffffffu, rmax0, 2));
        rmax1 = fmaxf(rmax1, __shfl_xor_sync(0xffffffffu, rmax1, 1));
        rmax1 = fmaxf(rmax1, __shfl_xor_sync(0xffffffffu, rmax1, 2));
        float mn0 = fmaxf(m0v, rmax0), mn1 = fmaxf(m1v, rmax1);
        float corr0 = fast_exp2(m0v - mn0), corr1 = fast_exp2(m1v - mn1);
        m0v = mn0; m1v = mn1;
        #pragma unroll
        for (int dd = 0; dd < 8; dd++) {
            o[dd][0] *= corr0; o[dd][1] *= corr0;
            o[dd][2] *= corr1; o[dd][3] *= corr1;
        }

        float rs0 = 0.f, rs1 = 0.f;
        uint32_t pa[4][4];
        #pragma unroll
        for (int j = 0; j < 8; j++) {
            float p0 = fast_exp2(s[j][0] - mn0);
            float p1 = fast_exp2(s[j][1] - mn0);
            float p2 = fast_exp2(s[j][2] - mn1);
            float p3 = fast_exp2(s[j][3] - mn1);
            rs0 += p0 + p1; rs1 += p2 + p3;
            int jj = j >> 1;
            if ((j & 1) == 0) { pa[jj][0] = pack_h2(p0, p1); pa[jj][1] = pack_h2(p2, p3); }
            else              { pa[jj][2] = pack_h2(p0, p1); pa[jj][3] = pack_h2(p2, p3); }
        }
        rs0 += __shfl_xor_sync(0xffffffffu, rs0, 1);
        rs0 += __shfl_xor_sync(0xffffffffu, rs0, 2);
        rs1 += __shfl_xor_sync(0xffffffffu, rs1, 1);
        rs1 += __shfl_xor_sync(0xffffffffu, rs1, 2);
        l0 = l0 * corr0 + rs0;
        l1 = l1 * corr1 + rs1;

        // O += P V   (P fragments already in A layout)
        #pragma unroll
        for (int dd = 0; dd < 8; dd++) {
            const __half* vr = &Vc[(dd * 8 + gid) * KS + 2 * tig];
            #pragma unroll
            for (int jj = 0; jj < 4; jj++) {
                uint32_t b0 = *(const uint32_t*)(vr + jj * 16);
                uint32_t b1 = *(const uint32_t*)(vr + jj * 16 + 8);
                mma_f16(o[dd], pa[jj], b0, b1);
            }
        }
        __syncthreads();
        buf ^= 1;
    }

    float inv0 = 1.f / l0, inv1 = 1.f / l1;
    float* Ob = g_o + (size_t)bh * HD * N_TOK;     // [c][n] within (b), c = h*64+d
    #pragma unroll
    for (int dd = 0; dd < 8; dd++) {
        int d = dd * 8 + 2 * tig;
        Ob[(size_t)d * N_TOK + q0 + gid]           = o[dd][0] * inv0;
        Ob[(size_t)(d + 1) * N_TOK + q0 + gid]     = o[dd][1] * inv0;
        Ob[(size_t)d * N_TOK + q0 + gid + 8]       = o[dd][2] * inv1;
        Ob[(size_t)(d + 1) * N_TOK + q0 + gid + 8] = o[dd][3] * inv1;
    }
}

// ==================== 4) proj: TF32 MMA GEMM + bias + residual ====================
__global__ __launch_bounds__(256) void proj_mma_kernel(
    const float* __restrict__ x, const float* __restrict__ w,
    const float* __restrict__ bias, float* __restrict__ out)
{
    __shared__ float As[64 * 36];
    __shared__ float Bs[32 * 136];
    int n0 = blockIdx.x * 128, m0 = blockIdx.y * 64, b = blockIdx.z;
    int tid = threadIdx.x;
    int warp = tid >> 5, lane = tid & 31, gid = lane >> 2, tig = lane & 3;
    int wm = (warp & 1) * 32, wn = (warp >> 1) * 32;

    float acc[2][4][4] = {};
    const float* ob = g_o + (size_t)b * C_DIM * N_TOK;

    for (int k0 = 0; k0 < C_DIM; k0 += 32) {
        __syncthreads();
        #pragma unroll
        for (int i = 0; i < 2; i++) {
            int f = tid + i * 256;
            int m = f >> 3, k4 = (f & 7) * 4;
            float4 wv = *(const float4*)&w[(size_t)(m0 + m) * C_DIM + k0 + k4];
            wv.x = tf32r(wv.x); wv.y = tf32r(wv.y); wv.z = tf32r(wv.z); wv.w = tf32r(wv.w);
            *(float4*)&As[m * 36 + k4] = wv;
        }
        #pragma unroll
        for (int i = 0; i < 4; i++) {
            int f = tid + i * 256;
            int kk = f >> 5, n4 = (f & 31) * 4;
            float4 xv = *(const float4*)&ob[(size_t)(k0 + kk) * N_TOK + n0 + n4];
            float4 r = make_float4(tf32r(xv.x), tf32r(xv.y), tf32r(xv.z), tf32r(xv.w));
            *(float4*)&Bs[kk * 136 + n4] = r;
        }
        __syncthreads();
        #pragma unroll
        for (int kk = 0; kk < 4; kk++) {
            int k = kk * 8;
            uint32_t af[2][4];
            #pragma unroll
            for (int mt = 0; mt < 2; mt++) {
                const float* ap = &As[(wm + mt * 16 + gid) * 36 + k + tig];
                af[mt][0] = __float_as_uint(ap[0]);
                af[mt][1] = __float_as_uint(ap[8 * 36]);
                af[mt][2] = __float_as_uint(ap[4]);
                af[mt][3] = __float_as_uint(ap[8 * 36 + 4]);
            }
            #pragma unroll
            for (int nt = 0; nt < 4; nt++) {
                uint32_t b0 = __float_as_uint(Bs[(k + tig) * 136 + wn + nt * 8 + gid]);
                uint32_t b1 = __float_as_uint(Bs[(k + tig + 4) * 136 + wn + nt * 8 + gid]);
                mma_tf32(acc[0][nt], af[0], b0, b1);
                mma_tf32(acc[1][nt], af[1], b0, b1);
            }
        }
    }

    #pragma unroll
    for (int mt = 0; mt < 2; mt++) {
        int m = m0 + wm + mt * 16 + gid;
        float bi0 = bias[m], bi1 = bias[m + 8];
        #pragma unroll
        for (int nt = 0; nt < 4; nt++) {
            int n = n0 + wn + nt * 8 + 2 * tig;
            size_t a0 = (size_t)(b * C_DIM + m) * N_TOK + n;
            size_t a1 = (size_t)(b * C_DIM + m + 8) * N_TOK + n;
            float2 r0 = *(const float2*)&x[a0];
            float2 r1 = *(const float2*)&x[a1];
            float2 v0 = make_float2(acc[mt][nt][0] + bi0 + r0.x, acc[mt][nt][1] + bi0 + r0.y);
            float2 v1 = make_float2(acc[mt][nt][2] + bi1 + r1.x, acc[mt][nt][3] + bi1 + r1.y);
            *(float2*)&out[a0] = v0;
            *(float2*)&out[a1] = v1;
        }
    }
}

// ==================== launch ====================
extern "C" void kernel_launch(void* const* d_in, const int* in_sizes, int n_in,
                              void* d_out, int out_size) {
    const float* x      = (const float*)d_in[0];
    const float* gamma  = (const float*)d_in[1];
    const float* beta   = (const float*)d_in[2];
    const float* w_qkv  = (const float*)d_in[3];
    const float* b_qkv  = (const float*)d_in[4];
    const float* w_proj = (const float*)d_in[5];
    const float* b_proj = (const float*)d_in[6];
    float* out = (float*)d_out;

    gn_part_kernel<<<BATCH * GROUPS * GN_SPLIT, 256>>>(x);
    gn_fin_kernel<<<1, 32>>>();
    qkv_mma_kernel<<<dim3(N_TOK / 128, (3 * C_DIM) / 64, BATCH), 256>>>(x, gamma, beta, w_qkv, b_qkv);
    attn_kernel<<<dim3(N_TOK / 128, BATCH * HEADS), 256>>>();
    proj_mma_kernel<<<dim3(N_TOK / 128, C_DIM / 64, BATCH), 256>>>(x, w_proj, b_proj, out);
}

// round 5
// speedup vs baseline: 14.8000x; 1.1620x over previous
#include <cuda_runtime.h>
#include <cuda_fp16.h>
#include <math.h>
#include <stdint.h>

#define BATCH   2
#define C_DIM   256
#define N_TOK   4096
#define HEADS   4
#define HD      64
#define GROUPS  8
#define GCNT    ((C_DIM / GROUPS) * N_TOK)      // 131072 per (b,g)
#define GN_SPLIT 16

// -------- scratch --------
__device__ float  g_stats[BATCH * GROUPS * 2];               // mean, rstd
__device__ float2 g_part[BATCH * GROUPS * GN_SPLIT];
__device__ __half g_q [BATCH * HEADS * N_TOK * HD];          // [bh][n][d], pre-scaled
__device__ __half g_k [BATCH * HEADS * N_TOK * HD];          // [bh][n][d]
__device__ __half g_vt[BATCH * HEADS * HD * N_TOK];          // [bh][d][n]  (transposed!)
__device__ float  g_o [BATCH * C_DIM * N_TOK];               // [b][c][n] channel-major

__device__ __forceinline__ float fast_exp2(float x) {
    float r; asm("ex2.approx.ftz.f32 %0, %1;" : "=f"(r) : "f"(x)); return r;
}
__device__ __forceinline__ uint32_t h2exp2(uint32_t x) {
    uint32_t r; asm("ex2.approx.f16x2 %0, %1;" : "=r"(r) : "r"(x)); return r;
}
__device__ __forceinline__ float tf32r(float x) {
    uint32_t r; asm("cvt.rna.tf32.f32 %0, %1;" : "=r"(r) : "f"(x));
    return __uint_as_float(r);
}
__device__ __forceinline__ uint32_t pack_h2(float a, float b) {
    __half2 h = __floats2half2_rn(a, b); return *(uint32_t*)&h;
}
__device__ __forceinline__ void mma_tf32(float* c, const uint32_t* a, uint32_t b0, uint32_t b1) {
    asm volatile(
        "mma.sync.aligned.m16n8k8.row.col.f32.tf32.tf32.f32 "
        "{%0,%1,%2,%3}, {%4,%5,%6,%7}, {%8,%9}, {%0,%1,%2,%3};"
        : "+f"(c[0]), "+f"(c[1]), "+f"(c[2]), "+f"(c[3])
        : "r"(a[0]), "r"(a[1]), "r"(a[2]), "r"(a[3]), "r"(b0), "r"(b1));
}
__device__ __forceinline__ void mma_f16(float* c, const uint32_t* a, uint32_t b0, uint32_t b1) {
    asm volatile(
        "mma.sync.aligned.m16n8k16.row.col.f32.f16.f16.f32 "
        "{%0,%1,%2,%3}, {%4,%5,%6,%7}, {%8,%9}, {%0,%1,%2,%3};"
        : "+f"(c[0]), "+f"(c[1]), "+f"(c[2]), "+f"(c[3])
        : "r"(a[0]), "r"(a[1]), "r"(a[2]), "r"(a[3]), "r"(b0), "r"(b1));
}
__device__ __forceinline__ void ldsm4(uint32_t& r0, uint32_t& r1, uint32_t& r2, uint32_t& r3,
                                      uint32_t addr) {
    asm volatile("ldmatrix.sync.aligned.m8n8.x4.shared.b16 {%0,%1,%2,%3}, [%4];"
                 : "=r"(r0), "=r"(r1), "=r"(r2), "=r"(r3) : "r"(addr));
}

// ==================== 1) GroupNorm stats ====================
__global__ __launch_bounds__(256) void gn_part_kernel(const float* __restrict__ x) {
    int bg = blockIdx.x >> 4, part = blockIdx.x & 15;
    const float4* p = (const float4*)(x + (size_t)bg * GCNT + (size_t)part * (GCNT / GN_SPLIT));
    const int n4 = GCNT / GN_SPLIT / 4;     // 2048
    float s = 0.f, ss = 0.f;
    for (int i = threadIdx.x; i < n4; i += 256) {
        float4 v = p[i];
        s  += v.x + v.y + v.z + v.w;
        ss += v.x * v.x + v.y * v.y + v.z * v.z + v.w * v.w;
    }
    #pragma unroll
    for (int o = 16; o > 0; o >>= 1) {
        s  += __shfl_xor_sync(0xffffffffu, s, o);
        ss += __shfl_xor_sync(0xffffffffu, ss, o);
    }
    __shared__ float sh1[8], sh2[8];
    int w = threadIdx.x >> 5, lane = threadIdx.x & 31;
    if (lane == 0) { sh1[w] = s; sh2[w] = ss; }
    __syncthreads();
    if (threadIdx.x == 0) {
        float t1 = 0.f, t2 = 0.f;
        #pragma unroll
        for (int i = 0; i < 8; i++) { t1 += sh1[i]; t2 += sh2[i]; }
        g_part[blockIdx.x] = make_float2(t1, t2);
    }
}
__global__ void gn_fin_kernel() {
    int t = threadIdx.x;
    if (t < BATCH * GROUPS) {
        float s = 0.f, ss = 0.f;
        #pragma unroll
        for (int i = 0; i < GN_SPLIT; i++) {
            float2 v = g_part[t * GN_SPLIT + i];
            s += v.x; ss += v.y;
        }
        float mean = s * (1.f / GCNT);
        float var  = ss * (1.f / GCNT) - mean * mean;
        g_stats[t * 2]     = mean;
        g_stats[t * 2 + 1] = rsqrtf(var + 1e-5f);
    }
}

// ==================== 2) QKV: TF32 MMA GEMM + GN fused ====================
__global__ __launch_bounds__(256) void qkv_mma_kernel(
    const float* __restrict__ x, const float* __restrict__ gamma,
    const float* __restrict__ beta, const float* __restrict__ w,
    const float* __restrict__ bias)
{
    __shared__ float coA[C_DIM], coB[C_DIM];
    __shared__ float As[64 * 36];
    __shared__ float Bs[32 * 136];
    int n0 = blockIdx.x * 128, m0 = blockIdx.y * 64, b = blockIdx.z;
    int tid = threadIdx.x;
    int warp = tid >> 5, lane = tid & 31, gid = lane >> 2, tig = lane & 3;
    int wm = (warp & 1) * 32, wn = (warp >> 1) * 32;

    {
        int c = tid;
        int sg = (b * GROUPS + (c >> 5)) * 2;
        float mean = g_stats[sg], rstd = g_stats[sg + 1];
        float a = rstd * gamma[c];
        coA[c] = a; coB[c] = beta[c] - mean * a;
    }

    float acc[2][4][4] = {};
    const float* xb = x + (size_t)b * C_DIM * N_TOK;

    for (int k0 = 0; k0 < C_DIM; k0 += 32) {
        __syncthreads();
        #pragma unroll
        for (int i = 0; i < 2; i++) {
            int f = tid + i * 256;
            int m = f >> 3, k4 = (f & 7) * 4;
            float4 wv = *(const float4*)&w[(size_t)(m0 + m) * C_DIM + k0 + k4];
            wv.x = tf32r(wv.x); wv.y = tf32r(wv.y); wv.z = tf32r(wv.z); wv.w = tf32r(wv.w);
            *(float4*)&As[m * 36 + k4] = wv;
        }
        #pragma unroll
        for (int i = 0; i < 4; i++) {
            int f = tid + i * 256;
            int kk = f >> 5, n4 = (f & 31) * 4;
            int c = k0 + kk;
            float4 xv = *(const float4*)&xb[(size_t)c * N_TOK + n0 + n4];
            float a = coA[c], bb = coB[c];
            float4 r = make_float4(tf32r(xv.x * a + bb), tf32r(xv.y * a + bb),
                                   tf32r(xv.z * a + bb), tf32r(xv.w * a + bb));
            *(float4*)&Bs[kk * 136 + n4] = r;
        }
        __syncthreads();
        #pragma unroll
        for (int kk = 0; kk < 4; kk++) {
            int k = kk * 8;
            uint32_t af[2][4];
            #pragma unroll
            for (int mt = 0; mt < 2; mt++) {
                const float* ap = &As[(wm + mt * 16 + gid) * 36 + k + tig];
                af[mt][0] = __float_as_uint(ap[0]);
                af[mt][1] = __float_as_uint(ap[8 * 36]);
                af[mt][2] = __float_as_uint(ap[4]);
                af[mt][3] = __float_as_uint(ap[8 * 36 + 4]);
            }
            #pragma unroll
            for (int nt = 0; nt < 4; nt++) {
                uint32_t b0 = __float_as_uint(Bs[(k + tig) * 136 + wn + nt * 8 + gid]);
                uint32_t b1 = __float_as_uint(Bs[(k + tig + 4) * 136 + wn + nt * 8 + gid]);
                mma_tf32(acc[0][nt], af[0], b0, b1);
                mma_tf32(acc[1][nt], af[1], b0, b1);
            }
        }
    }

    const float QSCALE = 0.125f * 1.4426950408889634f;
    int which = m0 >> 8;                 // 0:q 1:k 2:v
    int h     = (m0 >> 6) & 3;
    int bh    = b * HEADS + h;
    #pragma unroll
    for (int mt = 0; mt < 2; mt++) {
        int d  = wm + mt * 16 + gid;
        float bi0 = bias[m0 + d], bi1 = bias[m0 + d + 8];
        #pragma unroll
        for (int nt = 0; nt < 4; nt++) {
            int n = n0 + wn + nt * 8 + 2 * tig;
            float v0 = acc[mt][nt][0] + bi0, v1 = acc[mt][nt][1] + bi0;
            float v2 = acc[mt][nt][2] + bi1, v3 = acc[mt][nt][3] + bi1;
            if (which == 0) {
                v0 *= QSCALE; v1 *= QSCALE; v2 *= QSCALE; v3 *= QSCALE;
                __half* q = g_q + ((size_t)bh * N_TOK) * HD;
                q[(size_t)n * HD + d]           = __float2half_rn(v0);
                q[(size_t)(n + 1) * HD + d]     = __float2half_rn(v1);
                q[(size_t)n * HD + d + 8]       = __float2half_rn(v2);
                q[(size_t)(n + 1) * HD + d + 8] = __float2half_rn(v3);
            } else if (which == 1) {
                __half* kq = g_k + ((size_t)bh * N_TOK) * HD;
                kq[(size_t)n * HD + d]           = __float2half_rn(v0);
                kq[(size_t)(n + 1) * HD + d]     = __float2half_rn(v1);
                kq[(size_t)n * HD + d + 8]       = __float2half_rn(v2);
                kq[(size_t)(n + 1) * HD + d + 8] = __float2half_rn(v3);
            } else {
                __half* vt = g_vt + ((size_t)bh * HD) * N_TOK;
                uint32_t u0 = pack_h2(v0, v1), u1 = pack_h2(v2, v3);
                *(uint32_t*)&vt[(size_t)d * N_TOK + n]       = u0;
                *(uint32_t*)&vt[(size_t)(d + 8) * N_TOK + n] = u1;
            }
        }
    }
}

// ==================== 3) Flash attention (fp16 mma, 32q/warp, ldmatrix, f16x2 exp) ====================
#define KS 72
__global__ __launch_bounds__(128, 2) void attn_kernel() {
    __shared__ __half Ks[2][64 * KS];
    __shared__ __half Vt[2][64 * KS];
    int bh   = blockIdx.y;
    int tid  = threadIdx.x;
    int warp = tid >> 5, lane = tid & 31, gid = lane >> 2, tig = lane & 3;
    int q0   = blockIdx.x * 128 + warp * 32;

    const __half* Qb = g_q  + (size_t)bh * N_TOK * HD;
    const __half* Kb = g_k  + (size_t)bh * N_TOK * HD;
    const __half* Vb = g_vt + (size_t)bh * HD * N_TOK;

    uint32_t ks_sh[2], vt_sh[2];
    ks_sh[0] = (uint32_t)__cvta_generic_to_shared(&Ks[0][0]);
    ks_sh[1] = (uint32_t)__cvta_generic_to_shared(&Ks[1][0]);
    vt_sh[0] = (uint32_t)__cvta_generic_to_shared(&Vt[0][0]);
    vt_sh[1] = (uint32_t)__cvta_generic_to_shared(&Vt[1][0]);

    auto load_tile = [&](int kt, int buf) {
        #pragma unroll
        for (int i = 0; i < 4; i++) {
            int f = tid + i * 128;
            int row = f >> 3, seg = (f & 7) * 8;
            uint32_t kd = ks_sh[buf] + (row * KS + seg) * 2;
            uint32_t vd = vt_sh[buf] + (row * KS + seg) * 2;
            const __half* ksrc = &Kb[(size_t)(kt * 64 + row) * HD + seg];
            const __half* vsrc = &Vb[(size_t)row * N_TOK + kt * 64 + seg];
            asm volatile("cp.async.cg.shared.global [%0], [%1], 16;" :: "r"(kd), "l"(ksrc));
            asm volatile("cp.async.cg.shared.global [%0], [%1], 16;" :: "r"(vd), "l"(vsrc));
        }
        asm volatile("cp.async.commit_group;");
    };

    // Q fragments for two 16-row subtiles
    uint32_t qaA[4][4], qaB[4][4];
    #pragma unroll
    for (int dd = 0; dd < 4; dd++) {
        const __half* a0 = Qb + (size_t)(q0 + gid)      * HD + dd * 16 + 2 * tig;
        const __half* a1 = Qb + (size_t)(q0 + gid + 8)  * HD + dd * 16 + 2 * tig;
        const __half* b0 = Qb + (size_t)(q0 + 16 + gid)     * HD + dd * 16 + 2 * tig;
        const __half* b1 = Qb + (size_t)(q0 + 16 + gid + 8) * HD + dd * 16 + 2 * tig;
        qaA[dd][0] = *(const uint32_t*)a0; qaA[dd][1] = *(const uint32_t*)a1;
        qaA[dd][2] = *(const uint32_t*)(a0 + 8); qaA[dd][3] = *(const uint32_t*)(a1 + 8);
        qaB[dd][0] = *(const uint32_t*)b0; qaB[dd][1] = *(const uint32_t*)b1;
        qaB[dd][2] = *(const uint32_t*)(b0 + 8); qaB[dd][3] = *(const uint32_t*)(b1 + 8);
    }

    float oA[8][4] = {}, oB[8][4] = {};
    float m0A = -1e30f, m1A = -1e30f, l0A = 0.f, l1A = 0.f;
    float m0B = -1e30f, m1B = -1e30f, l0B = 0.f, l1B = 0.f;

    int ldrow = (lane & 7), ldseg = (lane >> 3) * 8;     // ldmatrix per-lane offsets
    int ldoff = ldrow * KS + ldseg;

    // softmax on one subtile: s -> pa, update m/l, rescale o
    auto softmax_tile = [&](float (&s)[8][4], float (&o)[8][4],
                            float& m0v, float& m1v, float& l0, float& l1,
                            uint32_t (&pa)[4][4]) {
        float rmax0 = -1e30f, rmax1 = -1e30f;
        #pragma unroll
        for (int j = 0; j < 8; j++) {
            rmax0 = fmaxf(rmax0, fmaxf(s[j][0], s[j][1]));
            rmax1 = fmaxf(rmax1, fmaxf(s[j][2], s[j][3]));
        }
        rmax0 = fmaxf(rmax0, __shfl_xor_sync(0xffffffffu, rmax0, 1));
        rmax0 = fmaxf(rmax0, __shfl_xor_sync(0xffffffffu, rmax0, 2));
        rmax1 = fmaxf(rmax1, __shfl_xor_sync(0xffffffffu, rmax1, 1));
        rmax1 = fmaxf(rmax1, __shfl_xor_sync(0xffffffffu, rmax1, 2));
        float mn0 = fmaxf(m0v, rmax0), mn1 = fmaxf(m1v, rmax1);

        #pragma unroll
        for (int j = 0; j < 8; j++) {
            uint32_t e0 = h2exp2(pack_h2(s[j][0] - mn0, s[j][1] - mn0));
            uint32_t e1 = h2exp2(pack_h2(s[j][2] - mn1, s[j][3] - mn1));
            int jj = j >> 1;
            if ((j & 1) == 0) { pa[jj][0] = e0; pa[jj][1] = e1; }
            else              { pa[jj][2] = e0; pa[jj][3] = e1; }
        }
        // row sums: group0 = pa[*][0], pa[*][2]; group1 = pa[*][1], pa[*][3]
        __half2 g0 = __hadd2(
            __hadd2(__hadd2(*(__half2*)&pa[0][0], *(__half2*)&pa[1][0]),
                    __hadd2(*(__half2*)&pa[2][0], *(__half2*)&pa[3][0])),
            __hadd2(__hadd2(*(__half2*)&pa[0][2], *(__half2*)&pa[1][2]),
                    __hadd2(*(__half2*)&pa[2][2], *(__half2*)&pa[3][2])));
        __half2 g1 = __hadd2(
            __hadd2(__hadd2(*(__half2*)&pa[0][1], *(__half2*)&pa[1][1]),
                    __hadd2(*(__half2*)&pa[2][1], *(__half2*)&pa[3][1])),
            __hadd2(__hadd2(*(__half2*)&pa[0][3], *(__half2*)&pa[1][3]),
                    __hadd2(*(__half2*)&pa[2][3], *(__half2*)&pa[3][3])));
        float2 f0 = __half22float2(g0), f1 = __half22float2(g1);
        float rs0 = f0.x + f0.y, rs1 = f1.x + f1.y;
        rs0 += __shfl_xor_sync(0xffffffffu, rs0, 1);
        rs0 += __shfl_xor_sync(0xffffffffu, rs0, 2);
        rs1 += __shfl_xor_sync(0xffffffffu, rs1, 1);
        rs1 += __shfl_xor_sync(0xffffffffu, rs1, 2);

        float corr0 = 1.f, corr1 = 1.f;
        bool upd = __any_sync(0xffffffffu, (mn0 > m0v) | (mn1 > m1v));
        if (upd) {
            corr0 = fast_exp2(m0v - mn0);
            corr1 = fast_exp2(m1v - mn1);
            #pragma unroll
            for (int dd = 0; dd < 8; dd++) {
                o[dd][0] *= corr0; o[dd][1] *= corr0;
                o[dd][2] *= corr1; o[dd][3] *= corr1;
            }
        }
        m0v = mn0; m1v = mn1;
        l0 = l0 * corr0 + rs0;
        l1 = l1 * corr1 + rs1;
    };

    load_tile(0, 0);
    int buf = 0;

    for (int kt = 0; kt < N_TOK / 64; kt++) {
        asm volatile("cp.async.wait_group 0;" ::: "memory");
        __syncthreads();
        if (kt + 1 < N_TOK / 64) load_tile(kt + 1, buf ^ 1);

        // ---- S = Q K^T (32 x 64), K frags shared across subtiles ----
        float sA[8][4], sB[8][4];
        #pragma unroll
        for (int j = 0; j < 8; j++) {
            sA[j][0] = sA[j][1] = sA[j][2] = sA[j][3] = 0.f;
            sB[j][0] = sB[j][1] = sB[j][2] = sB[j][3] = 0.f;
            #pragma unroll
            for (int half = 0; half < 2; half++) {
                uint32_t b0, b1, b2, b3;
                ldsm4(b0, b1, b2, b3, ks_sh[buf] + (j * 8 * KS + half * 32 + ldoff) * 2);
                mma_f16(sA[j], qaA[2 * half],     b0, b1);
                mma_f16(sA[j], qaA[2 * half + 1], b2, b3);
                mma_f16(sB[j], qaB[2 * half],     b0, b1);
                mma_f16(sB[j], qaB[2 * half + 1], b2, b3);
            }
        }

        uint32_t paA[4][4], paB[4][4];
        softmax_tile(sA, oA, m0A, m1A, l0A, l1A, paA);
        softmax_tile(sB, oB, m0B, m1B, l0B, l1B, paB);

        // ---- O += P V, V frags shared across subtiles ----
        #pragma unroll
        for (int dd = 0; dd < 8; dd++) {
            #pragma unroll
            for (int half = 0; half < 2; half++) {
                uint32_t b0, b1, b2, b3;
                ldsm4(b0, b1, b2, b3, vt_sh[buf] + (dd * 8 * KS + half * 32 + ldoff) * 2);
                mma_f16(oA[dd], paA[2 * half],     b0, b1);
                mma_f16(oA[dd], paA[2 * half + 1], b2, b3);
                mma_f16(oB[dd], paB[2 * half],     b0, b1);
                mma_f16(oB[dd], paB[2 * half + 1], b2, b3);
            }
        }
        __syncthreads();
        buf ^= 1;
    }

    float i0A = 1.f / l0A, i1A = 1.f / l1A;
    float i0B = 1.f / l0B, i1B = 1.f / l1B;
    float* Ob = g_o + (size_t)bh * HD * N_TOK;     // [c][n] within (b), c = h*64+d
    #pragma unroll
    for (int dd = 0; dd < 8; dd++) {
        int d = dd * 8 + 2 * tig;
        Ob[(size_t)d * N_TOK + q0 + gid]                = oA[dd][0] * i0A;
        Ob[(size_t)(d + 1) * N_TOK + q0 + gid]          = oA[dd][1] * i0A;
        Ob[(size_t)d * N_TOK + q0 + gid + 8]            = oA[dd][2] * i1A;
        Ob[(size_t)(d + 1) * N_TOK + q0 + gid + 8]      = oA[dd][3] * i1A;
        Ob[(size_t)d * N_TOK + q0 + 16 + gid]           = oB[dd][0] * i0B;
        Ob[(size_t)(d + 1) * N_TOK + q0 + 16 + gid]     = oB[dd][1] * i0B;
        Ob[(size_t)d * N_TOK + q0 + 16 + gid + 8]       = oB[dd][2] * i1B;
        Ob[(size_t)(d + 1) * N_TOK + q0 + 16 + gid + 8] = oB[dd][3] * i1B;
    }
}

// ==================== 4) proj: TF32 MMA GEMM + bias + residual ====================
__global__ __launch_bounds__(256) void proj_mma_kernel(
    const float* __restrict__ x, const float* __restrict__ w,
    const float* __restrict__ bias, float* __restrict__ out)
{
    __shared__ float As[64 * 36];
    __shared__ float Bs[32 * 136];
    int n0 = blockIdx.x * 128, m0 = blockIdx.y * 64, b = blockIdx.z;
    int tid = threadIdx.x;
    int warp = tid >> 5, lane = tid & 31, gid = lane >> 2, tig = lane & 3;
    int wm = (warp & 1) * 32, wn = (warp >> 1) * 32;

    float acc[2][4][4] = {};
    const float* ob = g_o + (size_t)b * C_DIM * N_TOK;

    for (int k0 = 0; k0 < C_DIM; k0 += 32) {
        __syncthreads();
        #pragma unroll
        for (int i = 0; i < 2; i++) {
            int f = tid + i * 256;
            int m = f >> 3, k4 = (f & 7) * 4;
            float4 wv = *(const float4*)&w[(size_t)(m0 + m) * C_DIM + k0 + k4];
            wv.x = tf32r(wv.x); wv.y = tf32r(wv.y); wv.z = tf32r(wv.z); wv.w = tf32r(wv.w);
            *(float4*)&As[m * 36 + k4] = wv;
        }
        #pragma unroll
        for (int i = 0; i < 4; i++) {
            int f = tid + i * 256;
            int kk = f >> 5, n4 = (f & 31) * 4;
            float4 xv = *(const float4*)&ob[(size_t)(k0 + kk) * N_TOK + n0 + n4];
            float4 r = make_float4(tf32r(xv.x), tf32r(xv.y), tf32r(xv.z), tf32r(xv.w));
            *(float4*)&Bs[kk * 136 + n4] = r;
        }
        __syncthreads();
        #pragma unroll
        for (int kk = 0; kk < 4; kk++) {
            int k = kk * 8;
            uint32_t af[2][4];
            #pragma unroll
            for (int mt = 0; mt < 2; mt++) {
                const float* ap = &As[(wm + mt * 16 + gid) * 36 + k + tig];
                af[mt][0] = __float_as_uint(ap[0]);
                af[mt][1] = __float_as_uint(ap[8 * 36]);
                af[mt][2] = __float_as_uint(ap[4]);
                af[mt][3] = __float_as_uint(ap[8 * 36 + 4]);
            }
            #pragma unroll
            for (int nt = 0; nt < 4; nt++) {
                uint32_t b0 = __float_as_uint(Bs[(k + tig) * 136 + wn + nt * 8 + gid]);
                uint32_t b1 = __float_as_uint(Bs[(k + tig + 4) * 136 + wn + nt * 8 + gid]);
                mma_tf32(acc[0][nt], af[0], b0, b1);
                mma_tf32(acc[1][nt], af[1], b0, b1);
            }
        }
    }

    #pragma unroll
    for (int mt = 0; mt < 2; mt++) {
        int m = m0 + wm + mt * 16 + gid;
        float bi0 = bias[m], bi1 = bias[m + 8];
        #pragma unroll
        for (int nt = 0; nt < 4; nt++) {
            int n = n0 + wn + nt * 8 + 2 * tig;
            size_t a0 = (size_t)(b * C_DIM + m) * N_TOK + n;
            size_t a1 = (size_t)(b * C_DIM + m + 8) * N_TOK + n;
            float2 r0 = *(const float2*)&x[a0];
            float2 r1 = *(const float2*)&x[a1];
            float2 v0 = make_float2(acc[mt][nt][0] + bi0 + r0.x, acc[mt][nt][1] + bi0 + r0.y);
            float2 v1 = make_float2(acc[mt][nt][2] + bi1 + r1.x, acc[mt][nt][3] + bi1 + r1.y);
            *(float2*)&out[a0] = v0;
            *(float2*)&out[a1] = v1;
        }
    }
}

// ==================== launch ====================
extern "C" void kernel_launch(void* const* d_in, const int* in_sizes, int n_in,
                              void* d_out, int out_size) {
    const float* x      = (const float*)d_in[0];
    const float* gamma  = (const float*)d_in[1];
    const float* beta   = (const float*)d_in[2];
    const float* w_qkv  = (const float*)d_in[3];
    const float* b_qkv  = (const float*)d_in[4];
    const float* w_proj = (const float*)d_in[5];
    const float* b_proj = (const float*)d_in[6];
    float* out = (float*)d_out;

    gn_part_kernel<<<BATCH * GROUPS * GN_SPLIT, 256>>>(x);
    gn_fin_kernel<<<1, 32>>>();
    qkv_mma_kernel<<<dim3(N_TOK / 128, (3 * C_DIM) / 64, BATCH), 256>>>(x, gamma, beta, w_qkv, b_qkv);
    attn_kernel<<<dim3(N_TOK / 128, BATCH * HEADS), 128>>>();
    proj_mma_kernel<<<dim3(N_TOK / 128, C_DIM / 64, BATCH), 256>>>(x, w_proj, b_proj, out);
}